// round 1
// baseline (speedup 1.0000x reference)
#include <cuda_runtime.h>
#include <cstdint>

// Problem constants
#define LSEQ 2048
#define BATCH 4
#define DMODEL 1024
#define NHEAD 16
#define HDIM 64
#define MROWS (LSEQ * BATCH)      // 8192
#define BHEADS (BATCH * NHEAD)    // 64

// ---------------- scratch (device globals; no allocation allowed) ----------
__device__ float g_q[(size_t)BHEADS * LSEQ * HDIM];     // 8.39M floats
__device__ float g_k[(size_t)BHEADS * LSEQ * HDIM];
__device__ float g_v[(size_t)BHEADS * LSEQ * HDIM];
__device__ float g_s[(size_t)BHEADS * LSEQ * LSEQ];     // 268.4M floats (scores -> probs in place)
__device__ float g_ctx[(size_t)MROWS * DMODEL];         // attention context, (L,B,D) layout

// ============================================================================
// GEMM: out = (X @ W^T + bias) * scale
// X: (M=8192, K=1024) row-major; W: (N=1024, K=1024) row-major (torch Linear)
// headmode=1: scatter n -> (h,d), m -> (l,b); write out[((b*H+h)*L + l)*HD + d]
// headmode=0: write out[m*D + n]
// Tiles: 128x128x16, 256 threads, 8x8 per-thread microtile.
// ============================================================================
__global__ __launch_bounds__(256) void gemm_xw(
    const float* __restrict__ X, const float* __restrict__ W,
    const float* __restrict__ bias, float* __restrict__ out,
    float scale, int headmode)
{
    __shared__ float Xs[16][128];
    __shared__ float Ws[16][128];

    const int tid = threadIdx.x;
    const int m0 = blockIdx.y * 128;
    const int n0 = blockIdx.x * 128;
    const int ty = tid >> 4;        // 0..15
    const int tx = tid & 15;        // 0..15

    float acc[8][8];
#pragma unroll
    for (int i = 0; i < 8; i++)
#pragma unroll
        for (int j = 0; j < 8; j++) acc[i][j] = 0.f;

    for (int k0 = 0; k0 < DMODEL; k0 += 16) {
        // stage X tile (transposed into Xs[k][m])
#pragma unroll
        for (int s = tid; s < 512; s += 256) {
            int row = s >> 2, kq = (s & 3) << 2;
            float4 v = *(const float4*)(X + (size_t)(m0 + row) * DMODEL + k0 + kq);
            Xs[kq + 0][row] = v.x; Xs[kq + 1][row] = v.y;
            Xs[kq + 2][row] = v.z; Xs[kq + 3][row] = v.w;
        }
        // stage W tile (transposed into Ws[k][n])
#pragma unroll
        for (int s = tid; s < 512; s += 256) {
            int row = s >> 2, kq = (s & 3) << 2;
            float4 v = *(const float4*)(W + (size_t)(n0 + row) * DMODEL + k0 + kq);
            Ws[kq + 0][row] = v.x; Ws[kq + 1][row] = v.y;
            Ws[kq + 2][row] = v.z; Ws[kq + 3][row] = v.w;
        }
        __syncthreads();

#pragma unroll
        for (int kk = 0; kk < 16; kk++) {
            float a[8], b[8];
#pragma unroll
            for (int i = 0; i < 8; i++) a[i] = Xs[kk][ty * 8 + i];
#pragma unroll
            for (int j = 0; j < 8; j++) b[j] = Ws[kk][tx * 8 + j];
#pragma unroll
            for (int i = 0; i < 8; i++)
#pragma unroll
                for (int j = 0; j < 8; j++) acc[i][j] = fmaf(a[i], b[j], acc[i][j]);
        }
        __syncthreads();
    }

#pragma unroll
    for (int i = 0; i < 8; i++) {
        int m = m0 + ty * 8 + i;
#pragma unroll
        for (int j = 0; j < 8; j++) {
            int n = n0 + tx * 8 + j;
            float v = (acc[i][j] + bias[n]) * scale;
            if (headmode) {
                int l = m >> 2;          // m = l*BATCH + b
                int b = m & 3;
                int h = n >> 6;          // n = h*HDIM + d
                int d = n & 63;
                g_q[0]; // no-op keeps compiler honest about globals visibility
                out[(((size_t)(b * NHEAD + h) * LSEQ + l) << 6) + d] = v;
            } else {
                out[(size_t)m * DMODEL + n] = v;
            }
        }
    }
}

// ============================================================================
// Scores: per head bh: S[q][k] = dot(Q[q,:], K[k,:])  (hd=64 contraction)
// Tiles: 128x128x16, 256 threads, 8x8 microtile. grid (16,16,64)
// ============================================================================
__global__ __launch_bounds__(256) void scores_kernel()
{
    __shared__ float Qs[16][128];
    __shared__ float Ks[16][128];

    const int bh = blockIdx.z;
    const float* __restrict__ Qh = g_q + (size_t)bh * LSEQ * HDIM;
    const float* __restrict__ Kh = g_k + (size_t)bh * LSEQ * HDIM;
    float* __restrict__ C = g_s + (size_t)bh * LSEQ * LSEQ;

    const int tid = threadIdx.x;
    const int m0 = blockIdx.y * 128;
    const int n0 = blockIdx.x * 128;
    const int ty = tid >> 4;
    const int tx = tid & 15;

    float acc[8][8];
#pragma unroll
    for (int i = 0; i < 8; i++)
#pragma unroll
        for (int j = 0; j < 8; j++) acc[i][j] = 0.f;

    for (int k0 = 0; k0 < HDIM; k0 += 16) {
#pragma unroll
        for (int s = tid; s < 512; s += 256) {
            int row = s >> 2, kq = (s & 3) << 2;
            float4 v = *(const float4*)(Qh + (size_t)(m0 + row) * HDIM + k0 + kq);
            Qs[kq + 0][row] = v.x; Qs[kq + 1][row] = v.y;
            Qs[kq + 2][row] = v.z; Qs[kq + 3][row] = v.w;
        }
#pragma unroll
        for (int s = tid; s < 512; s += 256) {
            int row = s >> 2, kq = (s & 3) << 2;
            float4 v = *(const float4*)(Kh + (size_t)(n0 + row) * HDIM + k0 + kq);
            Ks[kq + 0][row] = v.x; Ks[kq + 1][row] = v.y;
            Ks[kq + 2][row] = v.z; Ks[kq + 3][row] = v.w;
        }
        __syncthreads();

#pragma unroll
        for (int kk = 0; kk < 16; kk++) {
            float a[8], b[8];
#pragma unroll
            for (int i = 0; i < 8; i++) a[i] = Qs[kk][ty * 8 + i];
#pragma unroll
            for (int j = 0; j < 8; j++) b[j] = Ks[kk][tx * 8 + j];
#pragma unroll
            for (int i = 0; i < 8; i++)
#pragma unroll
                for (int j = 0; j < 8; j++) acc[i][j] = fmaf(a[i], b[j], acc[i][j]);
        }
        __syncthreads();
    }

#pragma unroll
    for (int i = 0; i < 8; i++) {
        int m = m0 + ty * 8 + i;
#pragma unroll
        for (int j = 0; j < 4; j++) {
            // vectorized 128-bit stores (n contiguous per thread group of 4)
            // (fall back to scalar for simplicity of index math)
            int n = n0 + tx * 8 + j * 2;
            C[(size_t)m * LSEQ + n]     = acc[i][j * 2];
            C[(size_t)m * LSEQ + n + 1] = acc[i][j * 2 + 1];
        }
    }
}

// ============================================================================
// Softmax (in place over g_s rows) + head-averaged weights.
// One block per (q, b) row; loops over 16 heads; 256 threads x 8 cols.
// ============================================================================
__global__ __launch_bounds__(256) void softmax_avg_kernel(float* __restrict__ avg_out)
{
    const int q = blockIdx.x;
    const int b = blockIdx.y;
    const int tid = threadIdx.x;
    const unsigned FULL = 0xffffffffu;
    __shared__ float sh[8];

    float av[8];
#pragma unroll
    for (int i = 0; i < 8; i++) av[i] = 0.f;

    for (int h = 0; h < NHEAD; h++) {
        float* __restrict__ row = g_s + ((size_t)(b * NHEAD + h) * LSEQ + q) * LSEQ;
        float4 v0 = *(const float4*)(row + tid * 8);
        float4 v1 = *(const float4*)(row + tid * 8 + 4);
        float p[8] = {v0.x, v0.y, v0.z, v0.w, v1.x, v1.y, v1.z, v1.w};

        // row max
        float mx = p[0];
#pragma unroll
        for (int i = 1; i < 8; i++) mx = fmaxf(mx, p[i]);
#pragma unroll
        for (int o = 16; o > 0; o >>= 1) mx = fmaxf(mx, __shfl_xor_sync(FULL, mx, o));
        if ((tid & 31) == 0) sh[tid >> 5] = mx;
        __syncthreads();
        mx = sh[0];
#pragma unroll
        for (int w = 1; w < 8; w++) mx = fmaxf(mx, sh[w]);
        __syncthreads();

        // exp + row sum
        float s = 0.f;
#pragma unroll
        for (int i = 0; i < 8; i++) { p[i] = __expf(p[i] - mx); s += p[i]; }
#pragma unroll
        for (int o = 16; o > 0; o >>= 1) s += __shfl_xor_sync(FULL, s, o);
        if ((tid & 31) == 0) sh[tid >> 5] = s;
        __syncthreads();
        s = 0.f;
#pragma unroll
        for (int w = 0; w < 8; w++) s += sh[w];
        __syncthreads();

        float inv = 1.0f / s;
#pragma unroll
        for (int i = 0; i < 8; i++) {
            p[i] *= inv;
            av[i] += p[i] * (1.0f / NHEAD);
        }
        float4 o0 = {p[0], p[1], p[2], p[3]};
        float4 o1 = {p[4], p[5], p[6], p[7]};
        *(float4*)(row + tid * 8)     = o0;
        *(float4*)(row + tid * 8 + 4) = o1;
    }

    float* __restrict__ arow = avg_out + ((size_t)b * LSEQ + q) * LSEQ + tid * 8;
    float4 a0 = {av[0], av[1], av[2], av[3]};
    float4 a1 = {av[4], av[5], av[6], av[7]};
    *(float4*)(arow)     = a0;
    *(float4*)(arow + 4) = a1;
}

// ============================================================================
// PV: per head bh: ctx_h[q][d] = sum_k P[q][k] * V[k][d]
// M=2048, N=64, K=2048. Tiles 128x64x16, 256 threads, 8x4 microtile.
// Writes directly into (L,B,D) layout context.
// grid (16, 64): x = q tile, y = bh
// ============================================================================
__global__ __launch_bounds__(256) void pv_kernel()
{
    __shared__ float Ps[16][128];
    __shared__ float Vs[16][64];

    const int bh = blockIdx.y;
    const int m0 = blockIdx.x * 128;
    const float* __restrict__ P = g_s + (size_t)bh * LSEQ * LSEQ;
    const float* __restrict__ V = g_v + (size_t)bh * LSEQ * HDIM;

    const int tid = threadIdx.x;
    const int ty = tid >> 4;     // 0..15 -> 8 rows each
    const int tx = tid & 15;     // 0..15 -> 4 cols each

    float acc[8][4];
#pragma unroll
    for (int i = 0; i < 8; i++)
#pragma unroll
        for (int j = 0; j < 4; j++) acc[i][j] = 0.f;

    for (int k0 = 0; k0 < LSEQ; k0 += 16) {
#pragma unroll
        for (int s = tid; s < 512; s += 256) {
            int row = s >> 2, kq = (s & 3) << 2;
            float4 v = *(const float4*)(P + (size_t)(m0 + row) * LSEQ + k0 + kq);
            Ps[kq + 0][row] = v.x; Ps[kq + 1][row] = v.y;
            Ps[kq + 2][row] = v.z; Ps[kq + 3][row] = v.w;
        }
        {
            int row = tid >> 4, dc = (tid & 15) << 2;
            float4 v = *(const float4*)(V + (size_t)(k0 + row) * HDIM + dc);
            *(float4*)&Vs[row][dc] = v;
        }
        __syncthreads();

#pragma unroll
        for (int kk = 0; kk < 16; kk++) {
            float a[8], bb[4];
#pragma unroll
            for (int i = 0; i < 8; i++) a[i] = Ps[kk][ty * 8 + i];
#pragma unroll
            for (int j = 0; j < 4; j++) bb[j] = Vs[kk][tx * 4 + j];
#pragma unroll
            for (int i = 0; i < 8; i++)
#pragma unroll
                for (int j = 0; j < 4; j++) acc[i][j] = fmaf(a[i], bb[j], acc[i][j]);
        }
        __syncthreads();
    }

    const int b = bh >> 4;   // bh = b*NHEAD + h
    const int h = bh & 15;
#pragma unroll
    for (int i = 0; i < 8; i++) {
        int qrow = m0 + ty * 8 + i;
#pragma unroll
        for (int j = 0; j < 4; j++) {
            int d = tx * 4 + j;
            g_ctx[((size_t)qrow * BATCH + b) * DMODEL + h * HDIM + d] = acc[i][j];
        }
    }
}

// ============================================================================
extern "C" void kernel_launch(void* const* d_in, const int* in_sizes, int n_in,
                              void* d_out, int out_size)
{
    const float* query = (const float*)d_in[0];
    const float* key_  = (const float*)d_in[1];
    const float* value = (const float*)d_in[2];
    const float* Wq = (const float*)d_in[3];
    const float* bq = (const float*)d_in[4];
    const float* Wk = (const float*)d_in[5];
    const float* bk = (const float*)d_in[6];
    const float* Wv = (const float*)d_in[7];
    const float* bv = (const float*)d_in[8];
    const float* Wo = (const float*)d_in[9];
    const float* bo = (const float*)d_in[10];

    float* out = (float*)d_out;                        // (L, B, D)
    float* avg = out + (size_t)MROWS * DMODEL;         // (B, L, L)

    float *pq, *pk, *pv, *pctx;
    cudaGetSymbolAddress((void**)&pq,   g_q);
    cudaGetSymbolAddress((void**)&pk,   g_k);
    cudaGetSymbolAddress((void**)&pv,   g_v);
    cudaGetSymbolAddress((void**)&pctx, g_ctx);

    const float scaling = 0.125f; // hd^-0.5 = 64^-0.5

    dim3 gp(DMODEL / 128, MROWS / 128);   // (8, 64)
    gemm_xw<<<gp, 256>>>(query, Wq, bq, pq, scaling, 1);
    gemm_xw<<<gp, 256>>>(key_,  Wk, bk, pk, 1.0f,    1);
    gemm_xw<<<gp, 256>>>(value, Wv, bv, pv, 1.0f,    1);

    scores_kernel<<<dim3(LSEQ / 128, LSEQ / 128, BHEADS), 256>>>();

    softmax_avg_kernel<<<dim3(LSEQ, BATCH), 256>>>(avg);

    pv_kernel<<<dim3(LSEQ / 128, BHEADS), 256>>>();

    gemm_xw<<<gp, 256>>>(pctx, Wo, bo, out, 1.0f, 0);
}

// round 2
// speedup vs baseline: 1.0006x; 1.0006x over previous
#include <cuda_runtime.h>
#include <cstdint>

// Problem constants
#define LSEQ 2048
#define BATCH 4
#define DMODEL 1024
#define NHEAD 16
#define HDIM 64
#define MROWS (LSEQ * BATCH)      // 8192
#define BHEADS (BATCH * NHEAD)    // 64

// ---------------- scratch (device globals; no allocation allowed) ----------
__device__ float g_q[(size_t)BHEADS * LSEQ * HDIM];     // 8.39M floats
__device__ float g_k[(size_t)BHEADS * LSEQ * HDIM];
__device__ float g_v[(size_t)BHEADS * LSEQ * HDIM];
__device__ float g_s[(size_t)BHEADS * LSEQ * LSEQ];     // 268.4M floats (scores -> probs in place)
__device__ float g_ctx[(size_t)MROWS * DMODEL];         // attention context, (L,B,D) layout

// ============================================================================
// GEMM: out = (X @ W^T + bias) * scale
// X: (M=8192, K=1024) row-major; W: (N=1024, K=1024) row-major (torch Linear)
// headmode=1: scatter n -> (h,d), m -> (l,b); write out[((b*H+h)*L + l)*HD + d]
// headmode=0: write out[m*D + n]
// Tiles: 128x128x16, 256 threads, 8x8 per-thread microtile.
// ============================================================================
__global__ __launch_bounds__(256) void gemm_xw(
    const float* __restrict__ X, const float* __restrict__ W,
    const float* __restrict__ bias, float* __restrict__ out,
    float scale, int headmode)
{
    __shared__ float Xs[16][128];
    __shared__ float Ws[16][128];

    const int tid = threadIdx.x;
    const int m0 = blockIdx.y * 128;
    const int n0 = blockIdx.x * 128;
    const int ty = tid >> 4;        // 0..15
    const int tx = tid & 15;        // 0..15

    float acc[8][8];
#pragma unroll
    for (int i = 0; i < 8; i++)
#pragma unroll
        for (int j = 0; j < 8; j++) acc[i][j] = 0.f;

    for (int k0 = 0; k0 < DMODEL; k0 += 16) {
        // stage X tile (transposed into Xs[k][m])
#pragma unroll
        for (int s = tid; s < 512; s += 256) {
            int row = s >> 2, kq = (s & 3) << 2;
            float4 v = *(const float4*)(X + (size_t)(m0 + row) * DMODEL + k0 + kq);
            Xs[kq + 0][row] = v.x; Xs[kq + 1][row] = v.y;
            Xs[kq + 2][row] = v.z; Xs[kq + 3][row] = v.w;
        }
        // stage W tile (transposed into Ws[k][n])
#pragma unroll
        for (int s = tid; s < 512; s += 256) {
            int row = s >> 2, kq = (s & 3) << 2;
            float4 v = *(const float4*)(W + (size_t)(n0 + row) * DMODEL + k0 + kq);
            Ws[kq + 0][row] = v.x; Ws[kq + 1][row] = v.y;
            Ws[kq + 2][row] = v.z; Ws[kq + 3][row] = v.w;
        }
        __syncthreads();

#pragma unroll
        for (int kk = 0; kk < 16; kk++) {
            float a[8], b[8];
#pragma unroll
            for (int i = 0; i < 8; i++) a[i] = Xs[kk][ty * 8 + i];
#pragma unroll
            for (int j = 0; j < 8; j++) b[j] = Ws[kk][tx * 8 + j];
#pragma unroll
            for (int i = 0; i < 8; i++)
#pragma unroll
                for (int j = 0; j < 8; j++) acc[i][j] = fmaf(a[i], b[j], acc[i][j]);
        }
        __syncthreads();
    }

#pragma unroll
    for (int i = 0; i < 8; i++) {
        int m = m0 + ty * 8 + i;
#pragma unroll
        for (int j = 0; j < 8; j++) {
            int n = n0 + tx * 8 + j;
            float v = (acc[i][j] + bias[n]) * scale;
            if (headmode) {
                int l = m >> 2;          // m = l*BATCH + b
                int b = m & 3;
                int h = n >> 6;          // n = h*HDIM + d
                int d = n & 63;
                g_q[0]; // no-op keeps compiler honest about globals visibility
                out[(((size_t)(b * NHEAD + h) * LSEQ + l) << 6) + d] = v;
            } else {
                out[(size_t)m * DMODEL + n] = v;
            }
        }
    }
}

// ============================================================================
// Scores: per head bh: S[q][k] = dot(Q[q,:], K[k,:])  (hd=64 contraction)
// Tiles: 128x128x16, 256 threads, 8x8 microtile. grid (16,16,64)
// ============================================================================
__global__ __launch_bounds__(256) void scores_kernel()
{
    __shared__ float Qs[16][128];
    __shared__ float Ks[16][128];

    const int bh = blockIdx.z;
    const float* __restrict__ Qh = g_q + (size_t)bh * LSEQ * HDIM;
    const float* __restrict__ Kh = g_k + (size_t)bh * LSEQ * HDIM;
    float* __restrict__ C = g_s + (size_t)bh * LSEQ * LSEQ;

    const int tid = threadIdx.x;
    const int m0 = blockIdx.y * 128;
    const int n0 = blockIdx.x * 128;
    const int ty = tid >> 4;
    const int tx = tid & 15;

    float acc[8][8];
#pragma unroll
    for (int i = 0; i < 8; i++)
#pragma unroll
        for (int j = 0; j < 8; j++) acc[i][j] = 0.f;

    for (int k0 = 0; k0 < HDIM; k0 += 16) {
#pragma unroll
        for (int s = tid; s < 512; s += 256) {
            int row = s >> 2, kq = (s & 3) << 2;
            float4 v = *(const float4*)(Qh + (size_t)(m0 + row) * HDIM + k0 + kq);
            Qs[kq + 0][row] = v.x; Qs[kq + 1][row] = v.y;
            Qs[kq + 2][row] = v.z; Qs[kq + 3][row] = v.w;
        }
#pragma unroll
        for (int s = tid; s < 512; s += 256) {
            int row = s >> 2, kq = (s & 3) << 2;
            float4 v = *(const float4*)(Kh + (size_t)(n0 + row) * HDIM + k0 + kq);
            Ks[kq + 0][row] = v.x; Ks[kq + 1][row] = v.y;
            Ks[kq + 2][row] = v.z; Ks[kq + 3][row] = v.w;
        }
        __syncthreads();

#pragma unroll
        for (int kk = 0; kk < 16; kk++) {
            float a[8], b[8];
#pragma unroll
            for (int i = 0; i < 8; i++) a[i] = Qs[kk][ty * 8 + i];
#pragma unroll
            for (int j = 0; j < 8; j++) b[j] = Ks[kk][tx * 8 + j];
#pragma unroll
            for (int i = 0; i < 8; i++)
#pragma unroll
                for (int j = 0; j < 8; j++) acc[i][j] = fmaf(a[i], b[j], acc[i][j]);
        }
        __syncthreads();
    }

#pragma unroll
    for (int i = 0; i < 8; i++) {
        int m = m0 + ty * 8 + i;
#pragma unroll
        for (int j = 0; j < 4; j++) {
            // vectorized 128-bit stores (n contiguous per thread group of 4)
            // (fall back to scalar for simplicity of index math)
            int n = n0 + tx * 8 + j * 2;
            C[(size_t)m * LSEQ + n]     = acc[i][j * 2];
            C[(size_t)m * LSEQ + n + 1] = acc[i][j * 2 + 1];
        }
    }
}

// ============================================================================
// Softmax (in place over g_s rows) + head-averaged weights.
// One block per (q, b) row; loops over 16 heads; 256 threads x 8 cols.
// ============================================================================
__global__ __launch_bounds__(256) void softmax_avg_kernel(float* __restrict__ avg_out)
{
    const int q = blockIdx.x;
    const int b = blockIdx.y;
    const int tid = threadIdx.x;
    const unsigned FULL = 0xffffffffu;
    __shared__ float sh[8];

    float av[8];
#pragma unroll
    for (int i = 0; i < 8; i++) av[i] = 0.f;

    for (int h = 0; h < NHEAD; h++) {
        float* __restrict__ row = g_s + ((size_t)(b * NHEAD + h) * LSEQ + q) * LSEQ;
        float4 v0 = *(const float4*)(row + tid * 8);
        float4 v1 = *(const float4*)(row + tid * 8 + 4);
        float p[8] = {v0.x, v0.y, v0.z, v0.w, v1.x, v1.y, v1.z, v1.w};

        // row max
        float mx = p[0];
#pragma unroll
        for (int i = 1; i < 8; i++) mx = fmaxf(mx, p[i]);
#pragma unroll
        for (int o = 16; o > 0; o >>= 1) mx = fmaxf(mx, __shfl_xor_sync(FULL, mx, o));
        if ((tid & 31) == 0) sh[tid >> 5] = mx;
        __syncthreads();
        mx = sh[0];
#pragma unroll
        for (int w = 1; w < 8; w++) mx = fmaxf(mx, sh[w]);
        __syncthreads();

        // exp + row sum
        float s = 0.f;
#pragma unroll
        for (int i = 0; i < 8; i++) { p[i] = __expf(p[i] - mx); s += p[i]; }
#pragma unroll
        for (int o = 16; o > 0; o >>= 1) s += __shfl_xor_sync(FULL, s, o);
        if ((tid & 31) == 0) sh[tid >> 5] = s;
        __syncthreads();
        s = 0.f;
#pragma unroll
        for (int w = 0; w < 8; w++) s += sh[w];
        __syncthreads();

        float inv = 1.0f / s;
#pragma unroll
        for (int i = 0; i < 8; i++) {
            p[i] *= inv;
            av[i] += p[i] * (1.0f / NHEAD);
        }
        float4 o0 = {p[0], p[1], p[2], p[3]};
        float4 o1 = {p[4], p[5], p[6], p[7]};
        *(float4*)(row + tid * 8)     = o0;
        *(float4*)(row + tid * 8 + 4) = o1;
    }

    float* __restrict__ arow = avg_out + ((size_t)b * LSEQ + q) * LSEQ + tid * 8;
    float4 a0 = {av[0], av[1], av[2], av[3]};
    float4 a1 = {av[4], av[5], av[6], av[7]};
    *(float4*)(arow)     = a0;
    *(float4*)(arow + 4) = a1;
}

// ============================================================================
// PV: per head bh: ctx_h[q][d] = sum_k P[q][k] * V[k][d]
// M=2048, N=64, K=2048. Tiles 128x64x16, 256 threads, 8x4 microtile.
// Writes directly into (L,B,D) layout context.
// grid (16, 64): x = q tile, y = bh
// ============================================================================
__global__ __launch_bounds__(256) void pv_kernel()
{
    __shared__ float Ps[16][128];
    __shared__ float Vs[16][64];

    const int bh = blockIdx.y;
    const int m0 = blockIdx.x * 128;
    const float* __restrict__ P = g_s + (size_t)bh * LSEQ * LSEQ;
    const float* __restrict__ V = g_v + (size_t)bh * LSEQ * HDIM;

    const int tid = threadIdx.x;
    const int ty = tid >> 4;     // 0..15 -> 8 rows each
    const int tx = tid & 15;     // 0..15 -> 4 cols each

    float acc[8][4];
#pragma unroll
    for (int i = 0; i < 8; i++)
#pragma unroll
        for (int j = 0; j < 4; j++) acc[i][j] = 0.f;

    for (int k0 = 0; k0 < LSEQ; k0 += 16) {
#pragma unroll
        for (int s = tid; s < 512; s += 256) {
            int row = s >> 2, kq = (s & 3) << 2;
            float4 v = *(const float4*)(P + (size_t)(m0 + row) * LSEQ + k0 + kq);
            Ps[kq + 0][row] = v.x; Ps[kq + 1][row] = v.y;
            Ps[kq + 2][row] = v.z; Ps[kq + 3][row] = v.w;
        }
        {
            int row = tid >> 4, dc = (tid & 15) << 2;
            float4 v = *(const float4*)(V + (size_t)(k0 + row) * HDIM + dc);
            *(float4*)&Vs[row][dc] = v;
        }
        __syncthreads();

#pragma unroll
        for (int kk = 0; kk < 16; kk++) {
            float a[8], bb[4];
#pragma unroll
            for (int i = 0; i < 8; i++) a[i] = Ps[kk][ty * 8 + i];
#pragma unroll
            for (int j = 0; j < 4; j++) bb[j] = Vs[kk][tx * 4 + j];
#pragma unroll
            for (int i = 0; i < 8; i++)
#pragma unroll
                for (int j = 0; j < 4; j++) acc[i][j] = fmaf(a[i], bb[j], acc[i][j]);
        }
        __syncthreads();
    }

    const int b = bh >> 4;   // bh = b*NHEAD + h
    const int h = bh & 15;
#pragma unroll
    for (int i = 0; i < 8; i++) {
        int qrow = m0 + ty * 8 + i;
#pragma unroll
        for (int j = 0; j < 4; j++) {
            int d = tx * 4 + j;
            g_ctx[((size_t)qrow * BATCH + b) * DMODEL + h * HDIM + d] = acc[i][j];
        }
    }
}

// ============================================================================
extern "C" void kernel_launch(void* const* d_in, const int* in_sizes, int n_in,
                              void* d_out, int out_size)
{
    const float* query = (const float*)d_in[0];
    const float* key_  = (const float*)d_in[1];
    const float* value = (const float*)d_in[2];
    const float* Wq = (const float*)d_in[3];
    const float* bq = (const float*)d_in[4];
    const float* Wk = (const float*)d_in[5];
    const float* bk = (const float*)d_in[6];
    const float* Wv = (const float*)d_in[7];
    const float* bv = (const float*)d_in[8];
    const float* Wo = (const float*)d_in[9];
    const float* bo = (const float*)d_in[10];

    float* out = (float*)d_out;                        // (L, B, D)
    float* avg = out + (size_t)MROWS * DMODEL;         // (B, L, L)

    float *pq, *pk, *pv, *pctx;
    cudaGetSymbolAddress((void**)&pq,   g_q);
    cudaGetSymbolAddress((void**)&pk,   g_k);
    cudaGetSymbolAddress((void**)&pv,   g_v);
    cudaGetSymbolAddress((void**)&pctx, g_ctx);

    const float scaling = 0.125f; // hd^-0.5 = 64^-0.5

    dim3 gp(DMODEL / 128, MROWS / 128);   // (8, 64)
    gemm_xw<<<gp, 256>>>(query, Wq, bq, pq, scaling, 1);
    gemm_xw<<<gp, 256>>>(key_,  Wk, bk, pk, 1.0f,    1);
    gemm_xw<<<gp, 256>>>(value, Wv, bv, pv, 1.0f,    1);

    scores_kernel<<<dim3(LSEQ / 128, LSEQ / 128, BHEADS), 256>>>();

    softmax_avg_kernel<<<dim3(LSEQ, BATCH), 256>>>(avg);

    pv_kernel<<<dim3(LSEQ / 128, BHEADS), 256>>>();

    gemm_xw<<<gp, 256>>>(pctx, Wo, bo, out, 1.0f, 0);
}

// round 3
// speedup vs baseline: 2.5281x; 2.5266x over previous
#include <cuda_runtime.h>
#include <cstdint>

// Problem constants
#define LSEQ 2048
#define BATCH 4
#define DMODEL 1024
#define NHEAD 16
#define HDIM 64
#define MROWS (LSEQ * BATCH)      // 8192
#define BHEADS (BATCH * NHEAD)    // 64

// ---------------- scratch (device globals; no allocation allowed) ----------
__device__ float g_q[(size_t)BHEADS * LSEQ * HDIM];
__device__ float g_k[(size_t)BHEADS * LSEQ * HDIM];
__device__ float g_v[(size_t)BHEADS * LSEQ * HDIM];
__device__ float g_s[(size_t)BHEADS * LSEQ * LSEQ];     // scores -> probs in place
__device__ float g_ctx[(size_t)MROWS * DMODEL];         // context, (L,B,D) layout

// ---------------- tf32 helpers ---------------------------------------------
__device__ __forceinline__ uint32_t f2tf32(float x) {
    uint32_t r;
    asm("cvt.rna.tf32.f32 %0, %1;" : "=r"(r) : "f"(x));
    return r;
}

__device__ __forceinline__ void mma8(float* d, const uint32_t* a,
                                     const uint32_t* b, const float* c) {
    asm volatile(
        "mma.sync.aligned.m16n8k8.row.col.f32.tf32.tf32.f32 "
        "{%0,%1,%2,%3}, {%4,%5,%6,%7}, {%8,%9}, {%10,%11,%12,%13};"
        : "=f"(d[0]), "=f"(d[1]), "=f"(d[2]), "=f"(d[3])
        : "r"(a[0]), "r"(a[1]), "r"(a[2]), "r"(a[3]),
          "r"(b[0]), "r"(b[1]),
          "f"(c[0]), "f"(c[1]), "f"(c[2]), "f"(c[3]));
}

// ============================================================================
// Projection / output GEMM on tensor cores (tf32).
// out = (X @ W^T + bias) * scale
// X: (8192, 1024) rm; W: (1024, 1024) rm (torch Linear).
// Block tile 128x128, K-tile 32, 8 warps (warp tile 64x32).
// headmode=1: scatter to per-head layout g_*[((b*H+h)*L + l)*64 + d]
// ============================================================================
__global__ __launch_bounds__(256) void gemm_tc(
    const float* __restrict__ X, const float* __restrict__ W,
    const float* __restrict__ bias, float* __restrict__ out,
    float scale, int headmode)
{
    __shared__ __align__(16) uint32_t As[128 * 36];
    __shared__ __align__(16) uint32_t Bs[128 * 36];

    const int tid = threadIdx.x;
    const int wid = tid >> 5, lane = tid & 31;
    const int g = lane >> 2, t = lane & 3;
    const int m0 = blockIdx.y * 128, n0 = blockIdx.x * 128;
    const int mw = (wid & 1) * 64, nw = (wid >> 1) * 32;

    float acc[4][4][4];
#pragma unroll
    for (int mi = 0; mi < 4; mi++)
#pragma unroll
        for (int ni = 0; ni < 4; ni++)
#pragma unroll
            for (int r = 0; r < 4; r++) acc[mi][ni][r] = 0.f;

    for (int k0 = 0; k0 < DMODEL; k0 += 32) {
#pragma unroll
        for (int s = tid; s < 1024; s += 256) {
            int row = s >> 3, q = (s & 7) << 2;
            float4 v = *(const float4*)(X + (size_t)(m0 + row) * DMODEL + k0 + q);
            uint4 u = make_uint4(f2tf32(v.x), f2tf32(v.y), f2tf32(v.z), f2tf32(v.w));
            *(uint4*)&As[row * 36 + q] = u;
        }
#pragma unroll
        for (int s = tid; s < 1024; s += 256) {
            int row = s >> 3, q = (s & 7) << 2;
            float4 v = *(const float4*)(W + (size_t)(n0 + row) * DMODEL + k0 + q);
            uint4 u = make_uint4(f2tf32(v.x), f2tf32(v.y), f2tf32(v.z), f2tf32(v.w));
            *(uint4*)&Bs[row * 36 + q] = u;
        }
        __syncthreads();

#pragma unroll
        for (int ks = 0; ks < 4; ks++) {
            const int kk = ks * 8;
            uint32_t af[4][4], bf[4][2];
#pragma unroll
            for (int mi = 0; mi < 4; mi++) {
                int m = mw + 16 * mi;
                af[mi][0] = As[(m + g) * 36 + kk + t];
                af[mi][1] = As[(m + g + 8) * 36 + kk + t];
                af[mi][2] = As[(m + g) * 36 + kk + t + 4];
                af[mi][3] = As[(m + g + 8) * 36 + kk + t + 4];
            }
#pragma unroll
            for (int ni = 0; ni < 4; ni++) {
                int n = nw + 8 * ni;
                bf[ni][0] = Bs[(n + g) * 36 + kk + t];
                bf[ni][1] = Bs[(n + g) * 36 + kk + t + 4];
            }
#pragma unroll
            for (int mi = 0; mi < 4; mi++)
#pragma unroll
                for (int ni = 0; ni < 4; ni++)
                    mma8(acc[mi][ni], af[mi], bf[ni], acc[mi][ni]);
        }
        __syncthreads();
    }

    // epilogue
#pragma unroll
    for (int ni = 0; ni < 4; ni++) {
        int n = n0 + nw + 8 * ni + 2 * t;
        float b0v = bias[n], b1v = bias[n + 1];
#pragma unroll
        for (int mi = 0; mi < 4; mi++) {
            int mA = m0 + mw + 16 * mi + g;
#pragma unroll
            for (int half = 0; half < 2; half++) {
                int m = mA + half * 8;
                float v0 = (acc[mi][ni][half * 2 + 0] + b0v) * scale;
                float v1 = (acc[mi][ni][half * 2 + 1] + b1v) * scale;
                float2 p = {v0, v1};
                if (headmode) {
                    int l = m >> 2, b = m & 3;
                    int h = n >> 6, d = n & 63;
                    *(float2*)&out[(((size_t)(b * NHEAD + h) * LSEQ + l) << 6) + d] = p;
                } else {
                    *(float2*)&out[(size_t)m * DMODEL + n] = p;
                }
            }
        }
    }
}

// ============================================================================
// Scores on tensor cores: per head, S[q][k] = dot(Q[q,:], K[k,:]), hd=64.
// Block 128x128, K-tiles 32 (2 iters), 8 warps (warp tile 64x32).
// grid (16, 16, 64)
// ============================================================================
__global__ __launch_bounds__(256) void scores_tc()
{
    __shared__ __align__(16) uint32_t As[128 * 36];
    __shared__ __align__(16) uint32_t Bs[128 * 36];

    const int bh = blockIdx.z;
    const float* __restrict__ Qh = g_q + (size_t)bh * LSEQ * HDIM;
    const float* __restrict__ Kh = g_k + (size_t)bh * LSEQ * HDIM;
    float* __restrict__ C = g_s + (size_t)bh * LSEQ * LSEQ;

    const int tid = threadIdx.x;
    const int wid = tid >> 5, lane = tid & 31;
    const int g = lane >> 2, t = lane & 3;
    const int m0 = blockIdx.y * 128, n0 = blockIdx.x * 128;
    const int mw = (wid & 1) * 64, nw = (wid >> 1) * 32;

    float acc[4][4][4];
#pragma unroll
    for (int mi = 0; mi < 4; mi++)
#pragma unroll
        for (int ni = 0; ni < 4; ni++)
#pragma unroll
            for (int r = 0; r < 4; r++) acc[mi][ni][r] = 0.f;

#pragma unroll
    for (int k0 = 0; k0 < HDIM; k0 += 32) {
#pragma unroll
        for (int s = tid; s < 1024; s += 256) {
            int row = s >> 3, q = (s & 7) << 2;
            float4 v = *(const float4*)(Qh + (size_t)(m0 + row) * HDIM + k0 + q);
            uint4 u = make_uint4(f2tf32(v.x), f2tf32(v.y), f2tf32(v.z), f2tf32(v.w));
            *(uint4*)&As[row * 36 + q] = u;
        }
#pragma unroll
        for (int s = tid; s < 1024; s += 256) {
            int row = s >> 3, q = (s & 7) << 2;
            float4 v = *(const float4*)(Kh + (size_t)(n0 + row) * HDIM + k0 + q);
            uint4 u = make_uint4(f2tf32(v.x), f2tf32(v.y), f2tf32(v.z), f2tf32(v.w));
            *(uint4*)&Bs[row * 36 + q] = u;
        }
        __syncthreads();

#pragma unroll
        for (int ks = 0; ks < 4; ks++) {
            const int kk = ks * 8;
            uint32_t af[4][4], bf[4][2];
#pragma unroll
            for (int mi = 0; mi < 4; mi++) {
                int m = mw + 16 * mi;
                af[mi][0] = As[(m + g) * 36 + kk + t];
                af[mi][1] = As[(m + g + 8) * 36 + kk + t];
                af[mi][2] = As[(m + g) * 36 + kk + t + 4];
                af[mi][3] = As[(m + g + 8) * 36 + kk + t + 4];
            }
#pragma unroll
            for (int ni = 0; ni < 4; ni++) {
                int n = nw + 8 * ni;
                bf[ni][0] = Bs[(n + g) * 36 + kk + t];
                bf[ni][1] = Bs[(n + g) * 36 + kk + t + 4];
            }
#pragma unroll
            for (int mi = 0; mi < 4; mi++)
#pragma unroll
                for (int ni = 0; ni < 4; ni++)
                    mma8(acc[mi][ni], af[mi], bf[ni], acc[mi][ni]);
        }
        __syncthreads();
    }

#pragma unroll
    for (int mi = 0; mi < 4; mi++) {
        int mA = m0 + mw + 16 * mi + g;
#pragma unroll
        for (int ni = 0; ni < 4; ni++) {
            int n = n0 + nw + 8 * ni + 2 * t;
#pragma unroll
            for (int half = 0; half < 2; half++) {
                int m = mA + half * 8;
                float2 p = {acc[mi][ni][half * 2 + 0], acc[mi][ni][half * 2 + 1]};
                *(float2*)&C[(size_t)m * LSEQ + n] = p;
            }
        }
    }
}

// ============================================================================
// Softmax (in place over g_s rows) + head-averaged weights.
// One block per (q, b) row; loops over 16 heads; 256 threads x 8 cols.
// ============================================================================
__global__ __launch_bounds__(256) void softmax_avg_kernel(float* __restrict__ avg_out)
{
    const int q = blockIdx.x;
    const int b = blockIdx.y;
    const int tid = threadIdx.x;
    const unsigned FULL = 0xffffffffu;
    __shared__ float sh[8];

    float av[8];
#pragma unroll
    for (int i = 0; i < 8; i++) av[i] = 0.f;

    for (int h = 0; h < NHEAD; h++) {
        float* __restrict__ row = g_s + ((size_t)(b * NHEAD + h) * LSEQ + q) * LSEQ;
        float4 v0 = *(const float4*)(row + tid * 8);
        float4 v1 = *(const float4*)(row + tid * 8 + 4);
        float p[8] = {v0.x, v0.y, v0.z, v0.w, v1.x, v1.y, v1.z, v1.w};

        float mx = p[0];
#pragma unroll
        for (int i = 1; i < 8; i++) mx = fmaxf(mx, p[i]);
#pragma unroll
        for (int o = 16; o > 0; o >>= 1) mx = fmaxf(mx, __shfl_xor_sync(FULL, mx, o));
        if ((tid & 31) == 0) sh[tid >> 5] = mx;
        __syncthreads();
        mx = sh[0];
#pragma unroll
        for (int w = 1; w < 8; w++) mx = fmaxf(mx, sh[w]);
        __syncthreads();

        float s = 0.f;
#pragma unroll
        for (int i = 0; i < 8; i++) { p[i] = __expf(p[i] - mx); s += p[i]; }
#pragma unroll
        for (int o = 16; o > 0; o >>= 1) s += __shfl_xor_sync(FULL, s, o);
        if ((tid & 31) == 0) sh[tid >> 5] = s;
        __syncthreads();
        s = 0.f;
#pragma unroll
        for (int w = 0; w < 8; w++) s += sh[w];
        __syncthreads();

        float inv = 1.0f / s;
#pragma unroll
        for (int i = 0; i < 8; i++) {
            p[i] *= inv;
            av[i] += p[i] * (1.0f / NHEAD);
        }
        float4 o0 = {p[0], p[1], p[2], p[3]};
        float4 o1 = {p[4], p[5], p[6], p[7]};
        *(float4*)(row + tid * 8)     = o0;
        *(float4*)(row + tid * 8 + 4) = o1;
    }

    float* __restrict__ arow = avg_out + ((size_t)b * LSEQ + q) * LSEQ + tid * 8;
    float4 a0 = {av[0], av[1], av[2], av[3]};
    float4 a1 = {av[4], av[5], av[6], av[7]};
    *(float4*)(arow)     = a0;
    *(float4*)(arow + 4) = a1;
}

// ============================================================================
// PV on tensor cores: per head, ctx[q][d] = sum_k P[q][k] * V[k][d].
// M=2048, N=64, K=2048. Block 128x64, K-tile 32, 8 warps (warp tile 32x32).
// grid (16, 64); writes into (L,B,D)-layout context.
// ============================================================================
__global__ __launch_bounds__(256) void pv_tc()
{
    __shared__ __align__(16) uint32_t Ps[128 * 36];
    __shared__ __align__(16) uint32_t Vs[32 * 72];

    const int bh = blockIdx.y;
    const int m0 = blockIdx.x * 128;
    const float* __restrict__ P = g_s + (size_t)bh * LSEQ * LSEQ;
    const float* __restrict__ V = g_v + (size_t)bh * LSEQ * HDIM;

    const int tid = threadIdx.x;
    const int wid = tid >> 5, lane = tid & 31;
    const int g = lane >> 2, t = lane & 3;
    const int mw = (wid & 3) * 32, nw = (wid >> 2) * 32;

    float acc[2][4][4];
#pragma unroll
    for (int mi = 0; mi < 2; mi++)
#pragma unroll
        for (int ni = 0; ni < 4; ni++)
#pragma unroll
            for (int r = 0; r < 4; r++) acc[mi][ni][r] = 0.f;

    for (int k0 = 0; k0 < LSEQ; k0 += 32) {
#pragma unroll
        for (int s = tid; s < 1024; s += 256) {
            int row = s >> 3, q = (s & 7) << 2;
            float4 v = *(const float4*)(P + (size_t)(m0 + row) * LSEQ + k0 + q);
            uint4 u = make_uint4(f2tf32(v.x), f2tf32(v.y), f2tf32(v.z), f2tf32(v.w));
            *(uint4*)&Ps[row * 36 + q] = u;
        }
#pragma unroll
        for (int s = tid; s < 512; s += 256) {
            int row = s >> 4, q = (s & 15) << 2;
            float4 v = *(const float4*)(V + (size_t)(k0 + row) * HDIM + q);
            uint4 u = make_uint4(f2tf32(v.x), f2tf32(v.y), f2tf32(v.z), f2tf32(v.w));
            *(uint4*)&Vs[row * 72 + q] = u;
        }
        __syncthreads();

#pragma unroll
        for (int ks = 0; ks < 4; ks++) {
            const int kk = ks * 8;
            uint32_t af[2][4], bf[4][2];
#pragma unroll
            for (int mi = 0; mi < 2; mi++) {
                int m = mw + 16 * mi;
                af[mi][0] = Ps[(m + g) * 36 + kk + t];
                af[mi][1] = Ps[(m + g + 8) * 36 + kk + t];
                af[mi][2] = Ps[(m + g) * 36 + kk + t + 4];
                af[mi][3] = Ps[(m + g + 8) * 36 + kk + t + 4];
            }
#pragma unroll
            for (int ni = 0; ni < 4; ni++) {
                int n = nw + 8 * ni;
                bf[ni][0] = Vs[(kk + t) * 72 + n + g];
                bf[ni][1] = Vs[(kk + t + 4) * 72 + n + g];
            }
#pragma unroll
            for (int mi = 0; mi < 2; mi++)
#pragma unroll
                for (int ni = 0; ni < 4; ni++)
                    mma8(acc[mi][ni], af[mi], bf[ni], acc[mi][ni]);
        }
        __syncthreads();
    }

    const int b = bh >> 4;
    const int h = bh & 15;
#pragma unroll
    for (int mi = 0; mi < 2; mi++) {
        int mA = m0 + mw + 16 * mi + g;
#pragma unroll
        for (int ni = 0; ni < 4; ni++) {
            int d = nw + 8 * ni + 2 * t;
#pragma unroll
            for (int half = 0; half < 2; half++) {
                int qrow = mA + half * 8;
                float2 p = {acc[mi][ni][half * 2 + 0], acc[mi][ni][half * 2 + 1]};
                *(float2*)&g_ctx[((size_t)qrow * BATCH + b) * DMODEL + h * HDIM + d] = p;
            }
        }
    }
}

// ============================================================================
extern "C" void kernel_launch(void* const* d_in, const int* in_sizes, int n_in,
                              void* d_out, int out_size)
{
    const float* query = (const float*)d_in[0];
    const float* key_  = (const float*)d_in[1];
    const float* value = (const float*)d_in[2];
    const float* Wq = (const float*)d_in[3];
    const float* bq = (const float*)d_in[4];
    const float* Wk = (const float*)d_in[5];
    const float* bk = (const float*)d_in[6];
    const float* Wv = (const float*)d_in[7];
    const float* bv = (const float*)d_in[8];
    const float* Wo = (const float*)d_in[9];
    const float* bo = (const float*)d_in[10];

    float* out = (float*)d_out;                        // (L, B, D)
    float* avg = out + (size_t)MROWS * DMODEL;         // (B, L, L)

    float *pq, *pk, *pv, *pctx;
    cudaGetSymbolAddress((void**)&pq,   g_q);
    cudaGetSymbolAddress((void**)&pk,   g_k);
    cudaGetSymbolAddress((void**)&pv,   g_v);
    cudaGetSymbolAddress((void**)&pctx, g_ctx);

    const float scaling = 0.125f; // hd^-0.5

    dim3 gp(DMODEL / 128, MROWS / 128);   // (8, 64)
    gemm_tc<<<gp, 256>>>(query, Wq, bq, pq, scaling, 1);
    gemm_tc<<<gp, 256>>>(key_,  Wk, bk, pk, 1.0f,    1);
    gemm_tc<<<gp, 256>>>(value, Wv, bv, pv, 1.0f,    1);

    scores_tc<<<dim3(LSEQ / 128, LSEQ / 128, BHEADS), 256>>>();

    softmax_avg_kernel<<<dim3(LSEQ, BATCH), 256>>>(avg);

    pv_tc<<<dim3(LSEQ / 128, BHEADS), 256>>>();

    gemm_tc<<<gp, 256>>>(pctx, Wo, bo, out, 1.0f, 0);
}

// round 4
// speedup vs baseline: 3.3456x; 1.3234x over previous
#include <cuda_runtime.h>
#include <cuda_fp16.h>
#include <cstdint>

// Problem constants
#define LSEQ 2048
#define BATCH 4
#define DMODEL 1024
#define NHEAD 16
#define HDIM 64
#define MROWS (LSEQ * BATCH)      // 8192
#define BHEADS (BATCH * NHEAD)    // 64

// ---------------- scratch (device globals; no allocation allowed) ----------
__device__ __half g_q[(size_t)BHEADS * LSEQ * HDIM];    // fp16 Q (head layout)
__device__ __half g_k[(size_t)BHEADS * LSEQ * HDIM];
__device__ __half g_v[(size_t)BHEADS * LSEQ * HDIM];
__device__ float  g_s[(size_t)BHEADS * LSEQ * LSEQ];    // raw scores fp32
__device__ __half g_p[(size_t)BHEADS * LSEQ * LSEQ];    // probs fp16
__device__ __half g_ctx[(size_t)MROWS * DMODEL];        // context fp16, (L,B,D)

// ---------------- fp16 mma m16n8k16 ----------------------------------------
__device__ __forceinline__ void mma16(float* d, const uint32_t* a,
                                      const uint32_t* b, const float* c) {
    asm volatile(
        "mma.sync.aligned.m16n8k16.row.col.f32.f16.f16.f32 "
        "{%0,%1,%2,%3}, {%4,%5,%6,%7}, {%8,%9}, {%10,%11,%12,%13};"
        : "=f"(d[0]), "=f"(d[1]), "=f"(d[2]), "=f"(d[3])
        : "r"(a[0]), "r"(a[1]), "r"(a[2]), "r"(a[3]),
          "r"(b[0]), "r"(b[1]),
          "f"(c[0]), "f"(c[1]), "f"(c[2]), "f"(c[3]));
}

__device__ __forceinline__ uint32_t pack_h2(float x, float y) {
    __half2 h = __floats2half2_rn(x, y);
    return *(uint32_t*)&h;
}

// ============================================================================
// Projection GEMM (fp32 in, fp16 head-scattered out).
// out = half( (X @ W^T + bias) * scale )
// X: (8192,1024) rm fp32; W: (1024,1024) rm fp32.
// Block 128x128, K-tile 32, 8 warps (warp tile 64x32).
// ============================================================================
__global__ __launch_bounds__(256) void gemm_proj(
    const float* __restrict__ X, const float* __restrict__ W,
    const float* __restrict__ bias, __half* __restrict__ out, float scale)
{
    __shared__ __align__(16) __half As[128 * 40];
    __shared__ __align__(16) __half Bs[128 * 40];

    const int tid = threadIdx.x;
    const int wid = tid >> 5, lane = tid & 31;
    const int g = lane >> 2, t = lane & 3;
    const int m0 = blockIdx.y * 128, n0 = blockIdx.x * 128;
    const int mw = (wid & 1) * 64, nw = (wid >> 1) * 32;

    float acc[4][4][4];
#pragma unroll
    for (int mi = 0; mi < 4; mi++)
#pragma unroll
        for (int ni = 0; ni < 4; ni++)
#pragma unroll
            for (int r = 0; r < 4; r++) acc[mi][ni][r] = 0.f;

    for (int k0 = 0; k0 < DMODEL; k0 += 32) {
#pragma unroll
        for (int s = tid; s < 1024; s += 256) {
            int row = s >> 3, q = (s & 7) << 2;
            float4 v = *(const float4*)(X + (size_t)(m0 + row) * DMODEL + k0 + q);
            uint2 u = {pack_h2(v.x, v.y), pack_h2(v.z, v.w)};
            *(uint2*)&As[row * 40 + q] = u;
        }
#pragma unroll
        for (int s = tid; s < 1024; s += 256) {
            int row = s >> 3, q = (s & 7) << 2;
            float4 v = *(const float4*)(W + (size_t)(n0 + row) * DMODEL + k0 + q);
            uint2 u = {pack_h2(v.x, v.y), pack_h2(v.z, v.w)};
            *(uint2*)&Bs[row * 40 + q] = u;
        }
        __syncthreads();

#pragma unroll
        for (int ks = 0; ks < 2; ks++) {
            const int kk = ks * 16;
            uint32_t af[4][4], bf[4][2];
#pragma unroll
            for (int mi = 0; mi < 4; mi++) {
                int m = mw + 16 * mi;
                af[mi][0] = *(const uint32_t*)&As[(m + g) * 40 + kk + 2 * t];
                af[mi][1] = *(const uint32_t*)&As[(m + g + 8) * 40 + kk + 2 * t];
                af[mi][2] = *(const uint32_t*)&As[(m + g) * 40 + kk + 2 * t + 8];
                af[mi][3] = *(const uint32_t*)&As[(m + g + 8) * 40 + kk + 2 * t + 8];
            }
#pragma unroll
            for (int ni = 0; ni < 4; ni++) {
                int n = nw + 8 * ni;
                bf[ni][0] = *(const uint32_t*)&Bs[(n + g) * 40 + kk + 2 * t];
                bf[ni][1] = *(const uint32_t*)&Bs[(n + g) * 40 + kk + 2 * t + 8];
            }
#pragma unroll
            for (int mi = 0; mi < 4; mi++)
#pragma unroll
                for (int ni = 0; ni < 4; ni++)
                    mma16(acc[mi][ni], af[mi], bf[ni], acc[mi][ni]);
        }
        __syncthreads();
    }

#pragma unroll
    for (int ni = 0; ni < 4; ni++) {
        int n = n0 + nw + 8 * ni + 2 * t;
        float b0v = bias[n], b1v = bias[n + 1];
#pragma unroll
        for (int mi = 0; mi < 4; mi++) {
            int mA = m0 + mw + 16 * mi + g;
#pragma unroll
            for (int half = 0; half < 2; half++) {
                int m = mA + half * 8;
                float v0 = (acc[mi][ni][half * 2 + 0] + b0v) * scale;
                float v1 = (acc[mi][ni][half * 2 + 1] + b1v) * scale;
                int l = m >> 2, b = m & 3;
                int h = n >> 6, d = n & 63;
                uint32_t u = pack_h2(v0, v1);
                *(uint32_t*)&out[(((size_t)(b * NHEAD + h) * LSEQ + l) << 6) + d] = u;
            }
        }
    }
}

// ============================================================================
// Scores: per head, S[q][k] = dot(Q[q,:], K[k,:]), hd=64, fp16 in, fp32 out.
// Block 128x128; whole K=64 staged once; 8 warps (warp tile 64x32).
// grid (16, 16, 64)
// ============================================================================
__global__ __launch_bounds__(256) void scores_h()
{
    __shared__ __align__(16) __half As[128 * 72];
    __shared__ __align__(16) __half Bs[128 * 72];

    const int bh = blockIdx.z;
    const __half* __restrict__ Qh = g_q + (size_t)bh * LSEQ * HDIM;
    const __half* __restrict__ Kh = g_k + (size_t)bh * LSEQ * HDIM;
    float* __restrict__ C = g_s + (size_t)bh * LSEQ * LSEQ;

    const int tid = threadIdx.x;
    const int wid = tid >> 5, lane = tid & 31;
    const int g = lane >> 2, t = lane & 3;
    const int m0 = blockIdx.y * 128, n0 = blockIdx.x * 128;
    const int mw = (wid & 1) * 64, nw = (wid >> 1) * 32;

    float acc[4][4][4];
#pragma unroll
    for (int mi = 0; mi < 4; mi++)
#pragma unroll
        for (int ni = 0; ni < 4; ni++)
#pragma unroll
            for (int r = 0; r < 4; r++) acc[mi][ni][r] = 0.f;

#pragma unroll
    for (int s = tid; s < 1024; s += 256) {
        int row = s >> 3, q = (s & 7) << 3;
        uint4 u = *(const uint4*)(Qh + (size_t)(m0 + row) * HDIM + q);
        *(uint4*)&As[row * 72 + q] = u;
    }
#pragma unroll
    for (int s = tid; s < 1024; s += 256) {
        int row = s >> 3, q = (s & 7) << 3;
        uint4 u = *(const uint4*)(Kh + (size_t)(n0 + row) * HDIM + q);
        *(uint4*)&Bs[row * 72 + q] = u;
    }
    __syncthreads();

#pragma unroll
    for (int ks = 0; ks < 4; ks++) {
        const int kk = ks * 16;
        uint32_t af[4][4], bf[4][2];
#pragma unroll
        for (int mi = 0; mi < 4; mi++) {
            int m = mw + 16 * mi;
            af[mi][0] = *(const uint32_t*)&As[(m + g) * 72 + kk + 2 * t];
            af[mi][1] = *(const uint32_t*)&As[(m + g + 8) * 72 + kk + 2 * t];
            af[mi][2] = *(const uint32_t*)&As[(m + g) * 72 + kk + 2 * t + 8];
            af[mi][3] = *(const uint32_t*)&As[(m + g + 8) * 72 + kk + 2 * t + 8];
        }
#pragma unroll
        for (int ni = 0; ni < 4; ni++) {
            int n = nw + 8 * ni;
            bf[ni][0] = *(const uint32_t*)&Bs[(n + g) * 72 + kk + 2 * t];
            bf[ni][1] = *(const uint32_t*)&Bs[(n + g) * 72 + kk + 2 * t + 8];
        }
#pragma unroll
        for (int mi = 0; mi < 4; mi++)
#pragma unroll
            for (int ni = 0; ni < 4; ni++)
                mma16(acc[mi][ni], af[mi], bf[ni], acc[mi][ni]);
    }

#pragma unroll
    for (int mi = 0; mi < 4; mi++) {
        int mA = m0 + mw + 16 * mi + g;
#pragma unroll
        for (int ni = 0; ni < 4; ni++) {
            int n = n0 + nw + 8 * ni + 2 * t;
#pragma unroll
            for (int half = 0; half < 2; half++) {
                int m = mA + half * 8;
                float2 p = {acc[mi][ni][half * 2 + 0], acc[mi][ni][half * 2 + 1]};
                *(float2*)&C[(size_t)m * LSEQ + n] = p;
            }
        }
    }
}

// ============================================================================
// Softmax: read fp32 scores, write fp16 probs + fp32 head-averaged weights.
// One block per (q, b) row; loops over 16 heads; 256 threads x 8 cols.
// ============================================================================
__global__ __launch_bounds__(256) void softmax_avg_kernel(float* __restrict__ avg_out)
{
    const int q = blockIdx.x;
    const int b = blockIdx.y;
    const int tid = threadIdx.x;
    const unsigned FULL = 0xffffffffu;
    __shared__ float sh[8];

    float av[8];
#pragma unroll
    for (int i = 0; i < 8; i++) av[i] = 0.f;

    for (int h = 0; h < NHEAD; h++) {
        const size_t roff = ((size_t)(b * NHEAD + h) * LSEQ + q) * LSEQ;
        const float* __restrict__ row = g_s + roff;
        float4 v0 = *(const float4*)(row + tid * 8);
        float4 v1 = *(const float4*)(row + tid * 8 + 4);
        float p[8] = {v0.x, v0.y, v0.z, v0.w, v1.x, v1.y, v1.z, v1.w};

        float mx = p[0];
#pragma unroll
        for (int i = 1; i < 8; i++) mx = fmaxf(mx, p[i]);
#pragma unroll
        for (int o = 16; o > 0; o >>= 1) mx = fmaxf(mx, __shfl_xor_sync(FULL, mx, o));
        if ((tid & 31) == 0) sh[tid >> 5] = mx;
        __syncthreads();
        mx = sh[0];
#pragma unroll
        for (int w = 1; w < 8; w++) mx = fmaxf(mx, sh[w]);
        __syncthreads();

        float s = 0.f;
#pragma unroll
        for (int i = 0; i < 8; i++) { p[i] = __expf(p[i] - mx); s += p[i]; }
#pragma unroll
        for (int o = 16; o > 0; o >>= 1) s += __shfl_xor_sync(FULL, s, o);
        if ((tid & 31) == 0) sh[tid >> 5] = s;
        __syncthreads();
        s = 0.f;
#pragma unroll
        for (int w = 0; w < 8; w++) s += sh[w];
        __syncthreads();

        float inv = 1.0f / s;
#pragma unroll
        for (int i = 0; i < 8; i++) {
            p[i] *= inv;
            av[i] += p[i] * (1.0f / NHEAD);
        }
        uint4 u = {pack_h2(p[0], p[1]), pack_h2(p[2], p[3]),
                   pack_h2(p[4], p[5]), pack_h2(p[6], p[7])};
        *(uint4*)&g_p[roff + tid * 8] = u;
    }

    float* __restrict__ arow = avg_out + ((size_t)b * LSEQ + q) * LSEQ + tid * 8;
    float4 a0 = {av[0], av[1], av[2], av[3]};
    float4 a1 = {av[4], av[5], av[6], av[7]};
    *(float4*)(arow)     = a0;
    *(float4*)(arow + 4) = a1;
}

// ============================================================================
// PV: per head, ctx[q][d] = sum_k P[q][k] * V[k][d], fp16 in, fp16 out.
// M=2048, N=64, K=2048. Block 128x64, K-tile 32, 8 warps (warp tile 32x32).
// V staged transposed (n-major) in smem.  grid (16, 64)
// ============================================================================
__global__ __launch_bounds__(256) void pv_h()
{
    __shared__ __align__(16) __half Ps[128 * 40];
    __shared__ __align__(16) __half Vs[64 * 40];

    const int bh = blockIdx.y;
    const int m0 = blockIdx.x * 128;
    const __half* __restrict__ P = g_p + (size_t)bh * LSEQ * LSEQ;
    const __half* __restrict__ V = g_v + (size_t)bh * LSEQ * HDIM;

    const int tid = threadIdx.x;
    const int wid = tid >> 5, lane = tid & 31;
    const int g = lane >> 2, t = lane & 3;
    const int mw = (wid & 3) * 32, nw = (wid >> 2) * 32;

    float acc[2][4][4];
#pragma unroll
    for (int mi = 0; mi < 2; mi++)
#pragma unroll
        for (int ni = 0; ni < 4; ni++)
#pragma unroll
            for (int r = 0; r < 4; r++) acc[mi][ni][r] = 0.f;

    for (int k0 = 0; k0 < LSEQ; k0 += 32) {
#pragma unroll
        for (int s = tid; s < 512; s += 256) {
            int row = s >> 2, q = (s & 3) << 3;
            uint4 u = *(const uint4*)(P + (size_t)(m0 + row) * LSEQ + k0 + q);
            *(uint4*)&Ps[row * 40 + q] = u;
        }
#pragma unroll
        for (int s = tid; s < 1024; s += 256) {
            int kr = s >> 5, n = (s & 31) << 1;
            __half2 v2 = *(const __half2*)(V + (size_t)(k0 + kr) * HDIM + n);
            Vs[n * 40 + kr]       = __low2half(v2);
            Vs[(n + 1) * 40 + kr] = __high2half(v2);
        }
        __syncthreads();

#pragma unroll
        for (int ks = 0; ks < 2; ks++) {
            const int kk = ks * 16;
            uint32_t af[2][4], bf[4][2];
#pragma unroll
            for (int mi = 0; mi < 2; mi++) {
                int m = mw + 16 * mi;
                af[mi][0] = *(const uint32_t*)&Ps[(m + g) * 40 + kk + 2 * t];
                af[mi][1] = *(const uint32_t*)&Ps[(m + g + 8) * 40 + kk + 2 * t];
                af[mi][2] = *(const uint32_t*)&Ps[(m + g) * 40 + kk + 2 * t + 8];
                af[mi][3] = *(const uint32_t*)&Ps[(m + g + 8) * 40 + kk + 2 * t + 8];
            }
#pragma unroll
            for (int ni = 0; ni < 4; ni++) {
                int n = nw + 8 * ni;
                bf[ni][0] = *(const uint32_t*)&Vs[(n + g) * 40 + kk + 2 * t];
                bf[ni][1] = *(const uint32_t*)&Vs[(n + g) * 40 + kk + 2 * t + 8];
            }
#pragma unroll
            for (int mi = 0; mi < 2; mi++)
#pragma unroll
                for (int ni = 0; ni < 4; ni++)
                    mma16(acc[mi][ni], af[mi], bf[ni], acc[mi][ni]);
        }
        __syncthreads();
    }

    const int b = bh >> 4;
    const int h = bh & 15;
#pragma unroll
    for (int mi = 0; mi < 2; mi++) {
        int mA = m0 + mw + 16 * mi + g;
#pragma unroll
        for (int ni = 0; ni < 4; ni++) {
            int d = nw + 8 * ni + 2 * t;
#pragma unroll
            for (int half = 0; half < 2; half++) {
                int qrow = mA + half * 8;
                uint32_t u = pack_h2(acc[mi][ni][half * 2 + 0], acc[mi][ni][half * 2 + 1]);
                *(uint32_t*)&g_ctx[((size_t)qrow * BATCH + b) * DMODEL + h * HDIM + d] = u;
            }
        }
    }
}

// ============================================================================
// Output projection: out = ctx @ Wo^T + bo   (ctx fp16, Wo fp32, out fp32).
// Block 128x128, K-tile 32, 8 warps.
// ============================================================================
__global__ __launch_bounds__(256) void gemm_out(
    const __half* __restrict__ Xh, const float* __restrict__ W,
    const float* __restrict__ bias, float* __restrict__ out)
{
    __shared__ __align__(16) __half As[128 * 40];
    __shared__ __align__(16) __half Bs[128 * 40];

    const int tid = threadIdx.x;
    const int wid = tid >> 5, lane = tid & 31;
    const int g = lane >> 2, t = lane & 3;
    const int m0 = blockIdx.y * 128, n0 = blockIdx.x * 128;
    const int mw = (wid & 1) * 64, nw = (wid >> 1) * 32;

    float acc[4][4][4];
#pragma unroll
    for (int mi = 0; mi < 4; mi++)
#pragma unroll
        for (int ni = 0; ni < 4; ni++)
#pragma unroll
            for (int r = 0; r < 4; r++) acc[mi][ni][r] = 0.f;

    for (int k0 = 0; k0 < DMODEL; k0 += 32) {
#pragma unroll
        for (int s = tid; s < 512; s += 256) {
            int row = s >> 2, q = (s & 3) << 3;
            uint4 u = *(const uint4*)(Xh + (size_t)(m0 + row) * DMODEL + k0 + q);
            *(uint4*)&As[row * 40 + q] = u;
        }
#pragma unroll
        for (int s = tid; s < 1024; s += 256) {
            int row = s >> 3, q = (s & 7) << 2;
            float4 v = *(const float4*)(W + (size_t)(n0 + row) * DMODEL + k0 + q);
            uint2 u = {pack_h2(v.x, v.y), pack_h2(v.z, v.w)};
            *(uint2*)&Bs[row * 40 + q] = u;
        }
        __syncthreads();

#pragma unroll
        for (int ks = 0; ks < 2; ks++) {
            const int kk = ks * 16;
            uint32_t af[4][4], bf[4][2];
#pragma unroll
            for (int mi = 0; mi < 4; mi++) {
                int m = mw + 16 * mi;
                af[mi][0] = *(const uint32_t*)&As[(m + g) * 40 + kk + 2 * t];
                af[mi][1] = *(const uint32_t*)&As[(m + g + 8) * 40 + kk + 2 * t];
                af[mi][2] = *(const uint32_t*)&As[(m + g) * 40 + kk + 2 * t + 8];
                af[mi][3] = *(const uint32_t*)&As[(m + g + 8) * 40 + kk + 2 * t + 8];
            }
#pragma unroll
            for (int ni = 0; ni < 4; ni++) {
                int n = nw + 8 * ni;
                bf[ni][0] = *(const uint32_t*)&Bs[(n + g) * 40 + kk + 2 * t];
                bf[ni][1] = *(const uint32_t*)&Bs[(n + g) * 40 + kk + 2 * t + 8];
            }
#pragma unroll
            for (int mi = 0; mi < 4; mi++)
#pragma unroll
                for (int ni = 0; ni < 4; ni++)
                    mma16(acc[mi][ni], af[mi], bf[ni], acc[mi][ni]);
        }
        __syncthreads();
    }

#pragma unroll
    for (int ni = 0; ni < 4; ni++) {
        int n = n0 + nw + 8 * ni + 2 * t;
        float b0v = bias[n], b1v = bias[n + 1];
#pragma unroll
        for (int mi = 0; mi < 4; mi++) {
            int mA = m0 + mw + 16 * mi + g;
#pragma unroll
            for (int half = 0; half < 2; half++) {
                int m = mA + half * 8;
                float2 p = {acc[mi][ni][half * 2 + 0] + b0v,
                            acc[mi][ni][half * 2 + 1] + b1v};
                *(float2*)&out[(size_t)m * DMODEL + n] = p;
            }
        }
    }
}

// ============================================================================
extern "C" void kernel_launch(void* const* d_in, const int* in_sizes, int n_in,
                              void* d_out, int out_size)
{
    const float* query = (const float*)d_in[0];
    const float* key_  = (const float*)d_in[1];
    const float* value = (const float*)d_in[2];
    const float* Wq = (const float*)d_in[3];
    const float* bq = (const float*)d_in[4];
    const float* Wk = (const float*)d_in[5];
    const float* bk = (const float*)d_in[6];
    const float* Wv = (const float*)d_in[7];
    const float* bv = (const float*)d_in[8];
    const float* Wo = (const float*)d_in[9];
    const float* bo = (const float*)d_in[10];

    float* out = (float*)d_out;                        // (L, B, D)
    float* avg = out + (size_t)MROWS * DMODEL;         // (B, L, L)

    __half *pq, *pk, *pv, *pctx;
    cudaGetSymbolAddress((void**)&pq,   g_q);
    cudaGetSymbolAddress((void**)&pk,   g_k);
    cudaGetSymbolAddress((void**)&pv,   g_v);
    cudaGetSymbolAddress((void**)&pctx, g_ctx);

    const float scaling = 0.125f; // hd^-0.5

    dim3 gp(DMODEL / 128, MROWS / 128);   // (8, 64)
    gemm_proj<<<gp, 256>>>(query, Wq, bq, pq, scaling);
    gemm_proj<<<gp, 256>>>(key_,  Wk, bk, pk, 1.0f);
    gemm_proj<<<gp, 256>>>(value, Wv, bv, pv, 1.0f);

    scores_h<<<dim3(LSEQ / 128, LSEQ / 128, BHEADS), 256>>>();

    softmax_avg_kernel<<<dim3(LSEQ, BATCH), 256>>>(avg);

    pv_h<<<dim3(LSEQ / 128, BHEADS), 256>>>();

    gemm_out<<<gp, 256>>>(pctx, Wo, bo, out);
}

// round 5
// speedup vs baseline: 3.4573x; 1.0334x over previous
#include <cuda_runtime.h>
#include <cuda_fp16.h>
#include <cstdint>

// Problem constants
#define LSEQ 2048
#define BATCH 4
#define DMODEL 1024
#define NHEAD 16
#define HDIM 64
#define MROWS (LSEQ * BATCH)      // 8192
#define BHEADS (BATCH * NHEAD)    // 64

// ---------------- scratch (device globals; no allocation allowed) ----------
__device__ __half g_q[(size_t)BHEADS * LSEQ * HDIM];    // fp16 Q (head layout)
__device__ __half g_k[(size_t)BHEADS * LSEQ * HDIM];
__device__ __half g_v[(size_t)BHEADS * LSEQ * HDIM];
__device__ float  g_s[(size_t)BHEADS * LSEQ * LSEQ];    // raw scores fp32
__device__ __half g_p[(size_t)BHEADS * LSEQ * LSEQ];    // probs fp16
__device__ __half g_ctx[(size_t)MROWS * DMODEL];        // context fp16, (L,B,D)
__device__ __half g_xh[3][(size_t)MROWS * DMODEL];      // fp16 copies of q/k/v inputs
__device__ __half g_wh[4][(size_t)DMODEL * DMODEL];     // fp16 copies of Wq/Wk/Wv/Wo

// ---------------- helpers ---------------------------------------------------
__device__ __forceinline__ void mma16(float* d, const uint32_t* a,
                                      const uint32_t* b, const float* c) {
    asm volatile(
        "mma.sync.aligned.m16n8k16.row.col.f32.f16.f16.f32 "
        "{%0,%1,%2,%3}, {%4,%5,%6,%7}, {%8,%9}, {%10,%11,%12,%13};"
        : "=f"(d[0]), "=f"(d[1]), "=f"(d[2]), "=f"(d[3])
        : "r"(a[0]), "r"(a[1]), "r"(a[2]), "r"(a[3]),
          "r"(b[0]), "r"(b[1]),
          "f"(c[0]), "f"(c[1]), "f"(c[2]), "f"(c[3]));
}

__device__ __forceinline__ void ldm_x4(uint32_t* r, uint32_t addr) {
    asm volatile("ldmatrix.sync.aligned.m8n8.x4.shared.b16 {%0,%1,%2,%3}, [%4];"
        : "=r"(r[0]), "=r"(r[1]), "=r"(r[2]), "=r"(r[3]) : "r"(addr));
}

__device__ __forceinline__ uint32_t pack_h2(float x, float y) {
    __half2 h = __floats2half2_rn(x, y);
    return *(uint32_t*)&h;
}

// fp32 -> fp16 convert (n multiple of 8)
__global__ __launch_bounds__(256) void cvt_f2h(const float* __restrict__ src,
                                               __half* __restrict__ dst, int n)
{
    int i = (blockIdx.x * 256 + threadIdx.x) * 8;
    if (i >= n) return;
    float4 a = *(const float4*)(src + i);
    float4 b = *(const float4*)(src + i + 4);
    uint4 u = {pack_h2(a.x, a.y), pack_h2(a.z, a.w),
               pack_h2(b.x, b.y), pack_h2(b.z, b.w)};
    *(uint4*)(dst + i) = u;
}

// ============================================================================
// Unified fp16 GEMM:  C = (X @ W^T + bias) * scale
// X: (8192,1024) fp16 rm; W: (1024,1024) fp16 rm.
// Block 128x128, K-tile 32, double-buffered smem, ldmatrix fragments.
// headmode=1: fp16 head-scattered out; headmode=0: fp32 plain out.
// ============================================================================
__global__ __launch_bounds__(256, 2) void gemm_h(
    const __half* __restrict__ X, const __half* __restrict__ W,
    const float* __restrict__ bias, void* __restrict__ outp,
    float scale, int headmode)
{
    __shared__ __align__(16) __half As[2][128 * 40];
    __shared__ __align__(16) __half Bs[2][128 * 40];

    const int tid = threadIdx.x;
    const int wid = tid >> 5, lane = tid & 31;
    const int g = lane >> 2, t = lane & 3;
    const int m0 = blockIdx.y * 128, n0 = blockIdx.x * 128;
    const int mw = (wid & 1) * 64, nw = (wid >> 1) * 32;
    // ldmatrix per-lane offsets
    const int lr = (lane & 7) + ((lane >> 3) & 1) * 8;   // row offset in 16
    const int lc = (lane >> 4) * 8;                      // col offset (halves)

    const int lrow = tid & 127, lcol = (tid >> 7) << 3;  // staging mapping

    float acc[4][4][4];
#pragma unroll
    for (int mi = 0; mi < 4; mi++)
#pragma unroll
        for (int ni = 0; ni < 4; ni++)
#pragma unroll
            for (int r = 0; r < 4; r++) acc[mi][ni][r] = 0.f;

    const __half* px = X + (size_t)(m0 + lrow) * DMODEL + lcol;
    const __half* pw = W + (size_t)(n0 + lrow) * DMODEL + lcol;

    uint4 xa[2], wb[2];
    xa[0] = *(const uint4*)(px);      xa[1] = *(const uint4*)(px + 16);
    wb[0] = *(const uint4*)(pw);      wb[1] = *(const uint4*)(pw + 16);
    {
        __half* pa = &As[0][lrow * 40 + lcol];
        __half* pb = &Bs[0][lrow * 40 + lcol];
        *(uint4*)pa = xa[0]; *(uint4*)(pa + 16) = xa[1];
        *(uint4*)pb = wb[0]; *(uint4*)(pb + 16) = wb[1];
    }
    __syncthreads();

    const int KT = DMODEL / 32;   // 32
    for (int kt = 0; kt < KT; kt++) {
        const int cur = kt & 1, nxt = cur ^ 1;
        if (kt + 1 < KT) {
            const __half* qx = px + (kt + 1) * 32;
            const __half* qw = pw + (kt + 1) * 32;
            xa[0] = *(const uint4*)(qx); xa[1] = *(const uint4*)(qx + 16);
            wb[0] = *(const uint4*)(qw); wb[1] = *(const uint4*)(qw + 16);
        }

        uint32_t as_base = (uint32_t)__cvta_generic_to_shared(&As[cur][0]);
        uint32_t bs_base = (uint32_t)__cvta_generic_to_shared(&Bs[cur][0]);
#pragma unroll
        for (int ks = 0; ks < 2; ks++) {
            const int kk = ks * 16;
            uint32_t a4[4][4], b4[2][4];
#pragma unroll
            for (int mi = 0; mi < 4; mi++)
                ldm_x4(a4[mi], as_base + ((mw + 16 * mi + lr) * 40 + kk + lc) * 2);
#pragma unroll
            for (int nj = 0; nj < 2; nj++)
                ldm_x4(b4[nj], bs_base + ((nw + 16 * nj + lr) * 40 + kk + lc) * 2);
#pragma unroll
            for (int mi = 0; mi < 4; mi++)
#pragma unroll
                for (int ni = 0; ni < 4; ni++) {
                    uint32_t bf[2] = {b4[ni >> 1][ni & 1], b4[ni >> 1][(ni & 1) + 2]};
                    mma16(acc[mi][ni], a4[mi], bf, acc[mi][ni]);
                }
        }

        if (kt + 1 < KT) {
            __half* pa = &As[nxt][lrow * 40 + lcol];
            __half* pb = &Bs[nxt][lrow * 40 + lcol];
            *(uint4*)pa = xa[0]; *(uint4*)(pa + 16) = xa[1];
            *(uint4*)pb = wb[0]; *(uint4*)(pb + 16) = wb[1];
        }
        __syncthreads();
    }

    // epilogue
#pragma unroll
    for (int ni = 0; ni < 4; ni++) {
        int n = n0 + nw + 8 * ni + 2 * t;
        float b0v = bias[n], b1v = bias[n + 1];
#pragma unroll
        for (int mi = 0; mi < 4; mi++) {
            int mA = m0 + mw + 16 * mi + g;
#pragma unroll
            for (int half = 0; half < 2; half++) {
                int m = mA + half * 8;
                float v0 = (acc[mi][ni][half * 2 + 0] + b0v) * scale;
                float v1 = (acc[mi][ni][half * 2 + 1] + b1v) * scale;
                if (headmode) {
                    int l = m >> 2, b = m & 3;
                    int h = n >> 6, d = n & 63;
                    uint32_t u = pack_h2(v0, v1);
                    *(uint32_t*)&((__half*)outp)[(((size_t)(b * NHEAD + h) * LSEQ + l) << 6) + d] = u;
                } else {
                    float2 p = {v0, v1};
                    *(float2*)&((float*)outp)[(size_t)m * DMODEL + n] = p;
                }
            }
        }
    }
}

// ============================================================================
// Scores: per head, S[q][k] = dot(Q[q,:], K[k,:]), hd=64, fp16 in, fp32 out.
// Block 128x128; whole K=64 staged once; ldmatrix fragments. grid (16,16,64)
// ============================================================================
__global__ __launch_bounds__(256, 3) void scores_h()
{
    __shared__ __align__(16) __half As[128 * 72];
    __shared__ __align__(16) __half Bs[128 * 72];

    const int bh = blockIdx.z;
    const __half* __restrict__ Qh = g_q + (size_t)bh * LSEQ * HDIM;
    const __half* __restrict__ Kh = g_k + (size_t)bh * LSEQ * HDIM;
    float* __restrict__ C = g_s + (size_t)bh * LSEQ * LSEQ;

    const int tid = threadIdx.x;
    const int wid = tid >> 5, lane = tid & 31;
    const int g = lane >> 2, t = lane & 3;
    const int m0 = blockIdx.y * 128, n0 = blockIdx.x * 128;
    const int mw = (wid & 1) * 64, nw = (wid >> 1) * 32;
    const int lr = (lane & 7) + ((lane >> 3) & 1) * 8;
    const int lc = (lane >> 4) * 8;

    float acc[4][4][4];
#pragma unroll
    for (int mi = 0; mi < 4; mi++)
#pragma unroll
        for (int ni = 0; ni < 4; ni++)
#pragma unroll
            for (int r = 0; r < 4; r++) acc[mi][ni][r] = 0.f;

#pragma unroll
    for (int s = tid; s < 1024; s += 256) {
        int row = s >> 3, q = (s & 7) << 3;
        uint4 u = *(const uint4*)(Qh + (size_t)(m0 + row) * HDIM + q);
        *(uint4*)&As[row * 72 + q] = u;
    }
#pragma unroll
    for (int s = tid; s < 1024; s += 256) {
        int row = s >> 3, q = (s & 7) << 3;
        uint4 u = *(const uint4*)(Kh + (size_t)(n0 + row) * HDIM + q);
        *(uint4*)&Bs[row * 72 + q] = u;
    }
    __syncthreads();

    uint32_t as_base = (uint32_t)__cvta_generic_to_shared(&As[0]);
    uint32_t bs_base = (uint32_t)__cvta_generic_to_shared(&Bs[0]);
#pragma unroll
    for (int ks = 0; ks < 4; ks++) {
        const int kk = ks * 16;
        uint32_t a4[4][4], b4[2][4];
#pragma unroll
        for (int mi = 0; mi < 4; mi++)
            ldm_x4(a4[mi], as_base + ((mw + 16 * mi + lr) * 72 + kk + lc) * 2);
#pragma unroll
        for (int nj = 0; nj < 2; nj++)
            ldm_x4(b4[nj], bs_base + ((nw + 16 * nj + lr) * 72 + kk + lc) * 2);
#pragma unroll
        for (int mi = 0; mi < 4; mi++)
#pragma unroll
            for (int ni = 0; ni < 4; ni++) {
                uint32_t bf[2] = {b4[ni >> 1][ni & 1], b4[ni >> 1][(ni & 1) + 2]};
                mma16(acc[mi][ni], a4[mi], bf, acc[mi][ni]);
            }
    }

#pragma unroll
    for (int mi = 0; mi < 4; mi++) {
        int mA = m0 + mw + 16 * mi + g;
#pragma unroll
        for (int ni = 0; ni < 4; ni++) {
            int n = n0 + nw + 8 * ni + 2 * t;
#pragma unroll
            for (int half = 0; half < 2; half++) {
                int m = mA + half * 8;
                float2 p = {acc[mi][ni][half * 2 + 0], acc[mi][ni][half * 2 + 1]};
                *(float2*)&C[(size_t)m * LSEQ + n] = p;
            }
        }
    }
}

// ============================================================================
// Softmax: fp32 scores -> fp16 probs + fp32 head-averaged weights.
// One block per (q,b) row; 16 heads with next-head prefetch.
// ============================================================================
__global__ __launch_bounds__(256) void softmax_avg_kernel(float* __restrict__ avg_out)
{
    const int q = blockIdx.x;
    const int b = blockIdx.y;
    const int tid = threadIdx.x;
    const unsigned FULL = 0xffffffffu;
    __shared__ float sh[8];

    float av[8];
#pragma unroll
    for (int i = 0; i < 8; i++) av[i] = 0.f;

    const size_t rbase = ((size_t)b * NHEAD * LSEQ + q) * LSEQ;   // head 0 row
    float4 c0 = *(const float4*)(g_s + rbase + tid * 8);
    float4 c1 = *(const float4*)(g_s + rbase + tid * 8 + 4);

    for (int h = 0; h < NHEAD; h++) {
        const size_t roff = rbase + (size_t)h * LSEQ * LSEQ;
        float4 n0, n1;
        if (h + 1 < NHEAD) {
            const size_t nf = roff + (size_t)LSEQ * LSEQ;
            n0 = *(const float4*)(g_s + nf + tid * 8);
            n1 = *(const float4*)(g_s + nf + tid * 8 + 4);
        }
        float p[8] = {c0.x, c0.y, c0.z, c0.w, c1.x, c1.y, c1.z, c1.w};

        float mx = p[0];
#pragma unroll
        for (int i = 1; i < 8; i++) mx = fmaxf(mx, p[i]);
#pragma unroll
        for (int o = 16; o > 0; o >>= 1) mx = fmaxf(mx, __shfl_xor_sync(FULL, mx, o));
        if ((tid & 31) == 0) sh[tid >> 5] = mx;
        __syncthreads();
        mx = sh[0];
#pragma unroll
        for (int w = 1; w < 8; w++) mx = fmaxf(mx, sh[w]);
        __syncthreads();

        float s = 0.f;
#pragma unroll
        for (int i = 0; i < 8; i++) { p[i] = __expf(p[i] - mx); s += p[i]; }
#pragma unroll
        for (int o = 16; o > 0; o >>= 1) s += __shfl_xor_sync(FULL, s, o);
        if ((tid & 31) == 0) sh[tid >> 5] = s;
        __syncthreads();
        s = 0.f;
#pragma unroll
        for (int w = 0; w < 8; w++) s += sh[w];
        __syncthreads();

        float inv = 1.0f / s;
#pragma unroll
        for (int i = 0; i < 8; i++) {
            p[i] *= inv;
            av[i] += p[i] * (1.0f / NHEAD);
        }
        uint4 u = {pack_h2(p[0], p[1]), pack_h2(p[2], p[3]),
                   pack_h2(p[4], p[5]), pack_h2(p[6], p[7])};
        *(uint4*)&g_p[roff + tid * 8] = u;

        c0 = n0; c1 = n1;
    }

    float* __restrict__ arow = avg_out + ((size_t)b * LSEQ + q) * LSEQ + tid * 8;
    float4 a0 = {av[0], av[1], av[2], av[3]};
    float4 a1 = {av[4], av[5], av[6], av[7]};
    *(float4*)(arow)     = a0;
    *(float4*)(arow + 4) = a1;
}

// ============================================================================
// PV: per head, ctx[q][d] = sum_k P[q][k] * V[k][d], fp16 in/out.
// M=2048, N=64, K=2048. Block 128x64, K-tile 32, double-buffered + ldmatrix.
// grid (16, 64)
// ============================================================================
__global__ __launch_bounds__(256, 2) void pv_h()
{
    __shared__ __align__(16) __half Ps[2][128 * 40];
    __shared__ __align__(16) __half Vs[2][64 * 40];

    const int bh = blockIdx.y;
    const int m0 = blockIdx.x * 128;
    const __half* __restrict__ P = g_p + (size_t)bh * LSEQ * LSEQ;
    const __half* __restrict__ V = g_v + (size_t)bh * LSEQ * HDIM;

    const int tid = threadIdx.x;
    const int wid = tid >> 5, lane = tid & 31;
    const int g = lane >> 2, t = lane & 3;
    const int mw = (wid & 3) * 32, nw = (wid >> 2) * 32;
    const int lr = (lane & 7) + ((lane >> 3) & 1) * 8;
    const int lc = (lane >> 4) * 8;

    const int lrow = tid & 127, lcol = (tid >> 7) << 3;     // P staging
    const __half* pp = P + (size_t)(m0 + lrow) * LSEQ + lcol;

    float acc[2][4][4];
#pragma unroll
    for (int mi = 0; mi < 2; mi++)
#pragma unroll
        for (int ni = 0; ni < 4; ni++)
#pragma unroll
            for (int r = 0; r < 4; r++) acc[mi][ni][r] = 0.f;

    uint4 pa[2];
    __half2 vr[4];
    // prologue: tile 0
    pa[0] = *(const uint4*)(pp);
    pa[1] = *(const uint4*)(pp + 16);
#pragma unroll
    for (int i = 0; i < 4; i++) {
        int idx = tid + 256 * i;
        vr[i] = *(const __half2*)(V + (size_t)(idx >> 5) * HDIM + ((idx & 31) << 1));
    }
    {
        __half* pd = &Ps[0][lrow * 40 + lcol];
        *(uint4*)pd = pa[0]; *(uint4*)(pd + 16) = pa[1];
#pragma unroll
        for (int i = 0; i < 4; i++) {
            int idx = tid + 256 * i;
            int kr = idx >> 5, n = (idx & 31) << 1;
            Vs[0][n * 40 + kr]       = __low2half(vr[i]);
            Vs[0][(n + 1) * 40 + kr] = __high2half(vr[i]);
        }
    }
    __syncthreads();

    const int KT = LSEQ / 32;   // 64
    for (int kt = 0; kt < KT; kt++) {
        const int cur = kt & 1, nxt = cur ^ 1;
        if (kt + 1 < KT) {
            const __half* qp = pp + (kt + 1) * 32;
            pa[0] = *(const uint4*)(qp);
            pa[1] = *(const uint4*)(qp + 16);
#pragma unroll
            for (int i = 0; i < 4; i++) {
                int idx = tid + 256 * i;
                vr[i] = *(const __half2*)(V + (size_t)((kt + 1) * 32 + (idx >> 5)) * HDIM
                                            + ((idx & 31) << 1));
            }
        }

        uint32_t ps_base = (uint32_t)__cvta_generic_to_shared(&Ps[cur][0]);
        uint32_t vs_base = (uint32_t)__cvta_generic_to_shared(&Vs[cur][0]);
#pragma unroll
        for (int ks = 0; ks < 2; ks++) {
            const int kk = ks * 16;
            uint32_t a4[2][4], b4[2][4];
#pragma unroll
            for (int mi = 0; mi < 2; mi++)
                ldm_x4(a4[mi], ps_base + ((mw + 16 * mi + lr) * 40 + kk + lc) * 2);
#pragma unroll
            for (int nj = 0; nj < 2; nj++)
                ldm_x4(b4[nj], vs_base + ((nw + 16 * nj + lr) * 40 + kk + lc) * 2);
#pragma unroll
            for (int mi = 0; mi < 2; mi++)
#pragma unroll
                for (int ni = 0; ni < 4; ni++) {
                    uint32_t bf[2] = {b4[ni >> 1][ni & 1], b4[ni >> 1][(ni & 1) + 2]};
                    mma16(acc[mi][ni], a4[mi], bf, acc[mi][ni]);
                }
        }

        if (kt + 1 < KT) {
            __half* pd = &Ps[nxt][lrow * 40 + lcol];
            *(uint4*)pd = pa[0]; *(uint4*)(pd + 16) = pa[1];
#pragma unroll
            for (int i = 0; i < 4; i++) {
                int idx = tid + 256 * i;
                int kr = idx >> 5, n = (idx & 31) << 1;
                Vs[nxt][n * 40 + kr]       = __low2half(vr[i]);
                Vs[nxt][(n + 1) * 40 + kr] = __high2half(vr[i]);
            }
        }
        __syncthreads();
    }

    const int b = bh >> 4;
    const int h = bh & 15;
#pragma unroll
    for (int mi = 0; mi < 2; mi++) {
        int mA = m0 + mw + 16 * mi + g;
#pragma unroll
        for (int ni = 0; ni < 4; ni++) {
            int d = nw + 8 * ni + 2 * t;
#pragma unroll
            for (int half = 0; half < 2; half++) {
                int qrow = mA + half * 8;
                uint32_t u = pack_h2(acc[mi][ni][half * 2 + 0], acc[mi][ni][half * 2 + 1]);
                *(uint32_t*)&g_ctx[((size_t)qrow * BATCH + b) * DMODEL + h * HDIM + d] = u;
            }
        }
    }
}

// ============================================================================
extern "C" void kernel_launch(void* const* d_in, const int* in_sizes, int n_in,
                              void* d_out, int out_size)
{
    const float* query = (const float*)d_in[0];
    const float* key_  = (const float*)d_in[1];
    const float* value = (const float*)d_in[2];
    const float* Wq = (const float*)d_in[3];
    const float* bq = (const float*)d_in[4];
    const float* Wk = (const float*)d_in[5];
    const float* bk = (const float*)d_in[6];
    const float* Wv = (const float*)d_in[7];
    const float* bv = (const float*)d_in[8];
    const float* Wo = (const float*)d_in[9];
    const float* bo = (const float*)d_in[10];

    float* out = (float*)d_out;                        // (L, B, D)
    float* avg = out + (size_t)MROWS * DMODEL;         // (B, L, L)

    __half *pq, *pk, *pv, *pctx, *pxh, *pwh;
    cudaGetSymbolAddress((void**)&pq,   g_q);
    cudaGetSymbolAddress((void**)&pk,   g_k);
    cudaGetSymbolAddress((void**)&pv,   g_v);
    cudaGetSymbolAddress((void**)&pctx, g_ctx);
    cudaGetSymbolAddress((void**)&pxh,  g_xh);
    cudaGetSymbolAddress((void**)&pwh,  g_wh);

    const size_t XSZ = (size_t)MROWS * DMODEL;     // 8.4M
    const size_t WSZ = (size_t)DMODEL * DMODEL;    // 1.05M

    // fp32 -> fp16 conversions
    const int CB = 256 * 8;
    cvt_f2h<<<(int)((XSZ + CB - 1) / CB), 256>>>(query, pxh + 0 * XSZ, (int)XSZ);
    cvt_f2h<<<(int)((XSZ + CB - 1) / CB), 256>>>(key_,  pxh + 1 * XSZ, (int)XSZ);
    cvt_f2h<<<(int)((XSZ + CB - 1) / CB), 256>>>(value, pxh + 2 * XSZ, (int)XSZ);
    cvt_f2h<<<(int)((WSZ + CB - 1) / CB), 256>>>(Wq, pwh + 0 * WSZ, (int)WSZ);
    cvt_f2h<<<(int)((WSZ + CB - 1) / CB), 256>>>(Wk, pwh + 1 * WSZ, (int)WSZ);
    cvt_f2h<<<(int)((WSZ + CB - 1) / CB), 256>>>(Wv, pwh + 2 * WSZ, (int)WSZ);
    cvt_f2h<<<(int)((WSZ + CB - 1) / CB), 256>>>(Wo, pwh + 3 * WSZ, (int)WSZ);

    const float scaling = 0.125f; // hd^-0.5

    dim3 gp(DMODEL / 128, MROWS / 128);   // (8, 64)
    gemm_h<<<gp, 256>>>(pxh + 0 * XSZ, pwh + 0 * WSZ, bq, pq, scaling, 1);
    gemm_h<<<gp, 256>>>(pxh + 1 * XSZ, pwh + 1 * WSZ, bk, pk, 1.0f,    1);
    gemm_h<<<gp, 256>>>(pxh + 2 * XSZ, pwh + 2 * WSZ, bv, pv, 1.0f,    1);

    scores_h<<<dim3(LSEQ / 128, LSEQ / 128, BHEADS), 256>>>();

    softmax_avg_kernel<<<dim3(LSEQ, BATCH), 256>>>(avg);

    pv_h<<<dim3(LSEQ / 128, BHEADS), 256>>>();

    gemm_h<<<gp, 256>>>(pctx, pwh + 3 * WSZ, bo, out, 1.0f, 0);
}

// round 6
// speedup vs baseline: 3.4594x; 1.0006x over previous
#include <cuda_runtime.h>
#include <cuda_fp16.h>
#include <cstdint>

// Problem constants
#define LSEQ 2048
#define BATCH 4
#define DMODEL 1024
#define NHEAD 16
#define HDIM 64
#define MROWS (LSEQ * BATCH)      // 8192
#define BHEADS (BATCH * NHEAD)    // 64

// ---------------- scratch (device globals; no allocation allowed) ----------
__device__ __half g_q[(size_t)BHEADS * LSEQ * HDIM];    // fp16 Q (head layout)
__device__ __half g_k[(size_t)BHEADS * LSEQ * HDIM];
__device__ __half g_v[(size_t)BHEADS * LSEQ * HDIM];
__device__ float  g_s[(size_t)BHEADS * LSEQ * LSEQ];    // raw scores fp32
__device__ __half g_p[(size_t)BHEADS * LSEQ * LSEQ];    // probs fp16
__device__ __half g_ctx[(size_t)MROWS * DMODEL];        // context fp16, (L,B,D)
__device__ __half g_xh[3][(size_t)MROWS * DMODEL];      // fp16 copies of q/k/v inputs
__device__ __half g_wh[4][(size_t)DMODEL * DMODEL];     // fp16 copies of Wq/Wk/Wv/Wo

// ---------------- helpers ---------------------------------------------------
__device__ __forceinline__ void mma16(float* d, const uint32_t* a,
                                      const uint32_t* b, const float* c) {
    asm volatile(
        "mma.sync.aligned.m16n8k16.row.col.f32.f16.f16.f32 "
        "{%0,%1,%2,%3}, {%4,%5,%6,%7}, {%8,%9}, {%10,%11,%12,%13};"
        : "=f"(d[0]), "=f"(d[1]), "=f"(d[2]), "=f"(d[3])
        : "r"(a[0]), "r"(a[1]), "r"(a[2]), "r"(a[3]),
          "r"(b[0]), "r"(b[1]),
          "f"(c[0]), "f"(c[1]), "f"(c[2]), "f"(c[3]));
}

__device__ __forceinline__ void ldm_x4(uint32_t* r, uint32_t addr) {
    asm volatile("ldmatrix.sync.aligned.m8n8.x4.shared.b16 {%0,%1,%2,%3}, [%4];"
        : "=r"(r[0]), "=r"(r[1]), "=r"(r[2]), "=r"(r[3]) : "r"(addr));
}

__device__ __forceinline__ uint32_t pack_h2(float x, float y) {
    __half2 h = __floats2half2_rn(x, y);
    return *(uint32_t*)&h;
}

// fp32 -> fp16 convert (n multiple of 8)
__global__ __launch_bounds__(256) void cvt_f2h(const float* __restrict__ src,
                                               __half* __restrict__ dst, int n)
{
    int i = (blockIdx.x * 256 + threadIdx.x) * 8;
    if (i >= n) return;
    float4 a = *(const float4*)(src + i);
    float4 b = *(const float4*)(src + i + 4);
    uint4 u = {pack_h2(a.x, a.y), pack_h2(a.z, a.w),
               pack_h2(b.x, b.y), pack_h2(b.z, b.w)};
    *(uint4*)(dst + i) = u;
}

// ============================================================================
// Unified fp16 GEMM:  C = (X @ W^T + bias) * scale
// X: (8192,1024) fp16 rm; W: (1024,1024) fp16 rm.
// Block 128x128, K-tile 32, double-buffered smem, ldmatrix fragments.
// headmode=1: fp16 head-scattered out; headmode=0: fp32 plain out.
// ============================================================================
__global__ __launch_bounds__(256, 2) void gemm_h(
    const __half* __restrict__ X, const __half* __restrict__ W,
    const float* __restrict__ bias, void* __restrict__ outp,
    float scale, int headmode)
{
    __shared__ __align__(16) __half As[2][128 * 40];
    __shared__ __align__(16) __half Bs[2][128 * 40];

    const int tid = threadIdx.x;
    const int wid = tid >> 5, lane = tid & 31;
    const int g = lane >> 2, t = lane & 3;
    const int m0 = blockIdx.y * 128, n0 = blockIdx.x * 128;
    const int mw = (wid & 1) * 64, nw = (wid >> 1) * 32;
    // ldmatrix per-lane offsets
    const int lr = (lane & 7) + ((lane >> 3) & 1) * 8;   // row offset in 16
    const int lc = (lane >> 4) * 8;                      // col offset (halves)

    const int lrow = tid & 127, lcol = (tid >> 7) << 3;  // staging mapping

    float acc[4][4][4];
#pragma unroll
    for (int mi = 0; mi < 4; mi++)
#pragma unroll
        for (int ni = 0; ni < 4; ni++)
#pragma unroll
            for (int r = 0; r < 4; r++) acc[mi][ni][r] = 0.f;

    const __half* px = X + (size_t)(m0 + lrow) * DMODEL + lcol;
    const __half* pw = W + (size_t)(n0 + lrow) * DMODEL + lcol;

    uint4 xa[2], wb[2];
    xa[0] = *(const uint4*)(px);      xa[1] = *(const uint4*)(px + 16);
    wb[0] = *(const uint4*)(pw);      wb[1] = *(const uint4*)(pw + 16);
    {
        __half* pa = &As[0][lrow * 40 + lcol];
        __half* pb = &Bs[0][lrow * 40 + lcol];
        *(uint4*)pa = xa[0]; *(uint4*)(pa + 16) = xa[1];
        *(uint4*)pb = wb[0]; *(uint4*)(pb + 16) = wb[1];
    }
    __syncthreads();

    const int KT = DMODEL / 32;   // 32
    for (int kt = 0; kt < KT; kt++) {
        const int cur = kt & 1, nxt = cur ^ 1;
        if (kt + 1 < KT) {
            const __half* qx = px + (kt + 1) * 32;
            const __half* qw = pw + (kt + 1) * 32;
            xa[0] = *(const uint4*)(qx); xa[1] = *(const uint4*)(qx + 16);
            wb[0] = *(const uint4*)(qw); wb[1] = *(const uint4*)(qw + 16);
        }

        uint32_t as_base = (uint32_t)__cvta_generic_to_shared(&As[cur][0]);
        uint32_t bs_base = (uint32_t)__cvta_generic_to_shared(&Bs[cur][0]);
#pragma unroll
        for (int ks = 0; ks < 2; ks++) {
            const int kk = ks * 16;
            uint32_t a4[4][4], b4[2][4];
#pragma unroll
            for (int mi = 0; mi < 4; mi++)
                ldm_x4(a4[mi], as_base + ((mw + 16 * mi + lr) * 40 + kk + lc) * 2);
#pragma unroll
            for (int nj = 0; nj < 2; nj++)
                ldm_x4(b4[nj], bs_base + ((nw + 16 * nj + lr) * 40 + kk + lc) * 2);
#pragma unroll
            for (int mi = 0; mi < 4; mi++)
#pragma unroll
                for (int ni = 0; ni < 4; ni++) {
                    uint32_t bf[2] = {b4[ni >> 1][ni & 1], b4[ni >> 1][(ni & 1) + 2]};
                    mma16(acc[mi][ni], a4[mi], bf, acc[mi][ni]);
                }
        }

        if (kt + 1 < KT) {
            __half* pa = &As[nxt][lrow * 40 + lcol];
            __half* pb = &Bs[nxt][lrow * 40 + lcol];
            *(uint4*)pa = xa[0]; *(uint4*)(pa + 16) = xa[1];
            *(uint4*)pb = wb[0]; *(uint4*)(pb + 16) = wb[1];
        }
        __syncthreads();
    }

    // epilogue
#pragma unroll
    for (int ni = 0; ni < 4; ni++) {
        int n = n0 + nw + 8 * ni + 2 * t;
        float b0v = bias[n], b1v = bias[n + 1];
#pragma unroll
        for (int mi = 0; mi < 4; mi++) {
            int mA = m0 + mw + 16 * mi + g;
#pragma unroll
            for (int half = 0; half < 2; half++) {
                int m = mA + half * 8;
                float v0 = (acc[mi][ni][half * 2 + 0] + b0v) * scale;
                float v1 = (acc[mi][ni][half * 2 + 1] + b1v) * scale;
                if (headmode) {
                    int l = m >> 2, b = m & 3;
                    int h = n >> 6, d = n & 63;
                    uint32_t u = pack_h2(v0, v1);
                    *(uint32_t*)&((__half*)outp)[(((size_t)(b * NHEAD + h) * LSEQ + l) << 6) + d] = u;
                } else {
                    float2 p = {v0, v1};
                    *(float2*)&((float*)outp)[(size_t)m * DMODEL + n] = p;
                }
            }
        }
    }
}

// ============================================================================
// Scores: per head, S[q][k] = dot(Q[q,:], K[k,:]), hd=64, fp16 in, fp32 out.
// Block 128x128; whole K=64 staged once; ldmatrix fragments. grid (16,16,64)
// ============================================================================
__global__ __launch_bounds__(256, 3) void scores_h()
{
    __shared__ __align__(16) __half As[128 * 72];
    __shared__ __align__(16) __half Bs[128 * 72];

    const int bh = blockIdx.z;
    const __half* __restrict__ Qh = g_q + (size_t)bh * LSEQ * HDIM;
    const __half* __restrict__ Kh = g_k + (size_t)bh * LSEQ * HDIM;
    float* __restrict__ C = g_s + (size_t)bh * LSEQ * LSEQ;

    const int tid = threadIdx.x;
    const int wid = tid >> 5, lane = tid & 31;
    const int g = lane >> 2, t = lane & 3;
    const int m0 = blockIdx.y * 128, n0 = blockIdx.x * 128;
    const int mw = (wid & 1) * 64, nw = (wid >> 1) * 32;
    const int lr = (lane & 7) + ((lane >> 3) & 1) * 8;
    const int lc = (lane >> 4) * 8;

    float acc[4][4][4];
#pragma unroll
    for (int mi = 0; mi < 4; mi++)
#pragma unroll
        for (int ni = 0; ni < 4; ni++)
#pragma unroll
            for (int r = 0; r < 4; r++) acc[mi][ni][r] = 0.f;

#pragma unroll
    for (int s = tid; s < 1024; s += 256) {
        int row = s >> 3, q = (s & 7) << 3;
        uint4 u = *(const uint4*)(Qh + (size_t)(m0 + row) * HDIM + q);
        *(uint4*)&As[row * 72 + q] = u;
    }
#pragma unroll
    for (int s = tid; s < 1024; s += 256) {
        int row = s >> 3, q = (s & 7) << 3;
        uint4 u = *(const uint4*)(Kh + (size_t)(n0 + row) * HDIM + q);
        *(uint4*)&Bs[row * 72 + q] = u;
    }
    __syncthreads();

    uint32_t as_base = (uint32_t)__cvta_generic_to_shared(&As[0]);
    uint32_t bs_base = (uint32_t)__cvta_generic_to_shared(&Bs[0]);
#pragma unroll
    for (int ks = 0; ks < 4; ks++) {
        const int kk = ks * 16;
        uint32_t a4[4][4], b4[2][4];
#pragma unroll
        for (int mi = 0; mi < 4; mi++)
            ldm_x4(a4[mi], as_base + ((mw + 16 * mi + lr) * 72 + kk + lc) * 2);
#pragma unroll
        for (int nj = 0; nj < 2; nj++)
            ldm_x4(b4[nj], bs_base + ((nw + 16 * nj + lr) * 72 + kk + lc) * 2);
#pragma unroll
        for (int mi = 0; mi < 4; mi++)
#pragma unroll
            for (int ni = 0; ni < 4; ni++) {
                uint32_t bf[2] = {b4[ni >> 1][ni & 1], b4[ni >> 1][(ni & 1) + 2]};
                mma16(acc[mi][ni], a4[mi], bf, acc[mi][ni]);
            }
    }

#pragma unroll
    for (int mi = 0; mi < 4; mi++) {
        int mA = m0 + mw + 16 * mi + g;
#pragma unroll
        for (int ni = 0; ni < 4; ni++) {
            int n = n0 + nw + 8 * ni + 2 * t;
#pragma unroll
            for (int half = 0; half < 2; half++) {
                int m = mA + half * 8;
                float2 p = {acc[mi][ni][half * 2 + 0], acc[mi][ni][half * 2 + 1]};
                *(float2*)&C[(size_t)m * LSEQ + n] = p;
            }
        }
    }
}

// ============================================================================
// Softmax: fp32 scores -> fp16 probs + fp32 head-averaged weights.
// One block per (q,b) row; 16 heads with next-head prefetch.
// ============================================================================
__global__ __launch_bounds__(256) void softmax_avg_kernel(float* __restrict__ avg_out)
{
    const int q = blockIdx.x;
    const int b = blockIdx.y;
    const int tid = threadIdx.x;
    const unsigned FULL = 0xffffffffu;
    __shared__ float sh[8];

    float av[8];
#pragma unroll
    for (int i = 0; i < 8; i++) av[i] = 0.f;

    const size_t rbase = ((size_t)b * NHEAD * LSEQ + q) * LSEQ;   // head 0 row
    float4 c0 = *(const float4*)(g_s + rbase + tid * 8);
    float4 c1 = *(const float4*)(g_s + rbase + tid * 8 + 4);

    for (int h = 0; h < NHEAD; h++) {
        const size_t roff = rbase + (size_t)h * LSEQ * LSEQ;
        float4 n0, n1;
        if (h + 1 < NHEAD) {
            const size_t nf = roff + (size_t)LSEQ * LSEQ;
            n0 = *(const float4*)(g_s + nf + tid * 8);
            n1 = *(const float4*)(g_s + nf + tid * 8 + 4);
        }
        float p[8] = {c0.x, c0.y, c0.z, c0.w, c1.x, c1.y, c1.z, c1.w};

        float mx = p[0];
#pragma unroll
        for (int i = 1; i < 8; i++) mx = fmaxf(mx, p[i]);
#pragma unroll
        for (int o = 16; o > 0; o >>= 1) mx = fmaxf(mx, __shfl_xor_sync(FULL, mx, o));
        if ((tid & 31) == 0) sh[tid >> 5] = mx;
        __syncthreads();
        mx = sh[0];
#pragma unroll
        for (int w = 1; w < 8; w++) mx = fmaxf(mx, sh[w]);
        __syncthreads();

        float s = 0.f;
#pragma unroll
        for (int i = 0; i < 8; i++) { p[i] = __expf(p[i] - mx); s += p[i]; }
#pragma unroll
        for (int o = 16; o > 0; o >>= 1) s += __shfl_xor_sync(FULL, s, o);
        if ((tid & 31) == 0) sh[tid >> 5] = s;
        __syncthreads();
        s = 0.f;
#pragma unroll
        for (int w = 0; w < 8; w++) s += sh[w];
        __syncthreads();

        float inv = 1.0f / s;
#pragma unroll
        for (int i = 0; i < 8; i++) {
            p[i] *= inv;
            av[i] += p[i] * (1.0f / NHEAD);
        }
        uint4 u = {pack_h2(p[0], p[1]), pack_h2(p[2], p[3]),
                   pack_h2(p[4], p[5]), pack_h2(p[6], p[7])};
        *(uint4*)&g_p[roff + tid * 8] = u;

        c0 = n0; c1 = n1;
    }

    float* __restrict__ arow = avg_out + ((size_t)b * LSEQ + q) * LSEQ + tid * 8;
    float4 a0 = {av[0], av[1], av[2], av[3]};
    float4 a1 = {av[4], av[5], av[6], av[7]};
    *(float4*)(arow)     = a0;
    *(float4*)(arow + 4) = a1;
}

// ============================================================================
// PV: per head, ctx[q][d] = sum_k P[q][k] * V[k][d], fp16 in/out.
// M=2048, N=64, K=2048. Block 128x64, K-tile 32, double-buffered + ldmatrix.
// grid (16, 64)
// ============================================================================
__global__ __launch_bounds__(256, 2) void pv_h()
{
    __shared__ __align__(16) __half Ps[2][128 * 40];
    __shared__ __align__(16) __half Vs[2][64 * 40];

    const int bh = blockIdx.y;
    const int m0 = blockIdx.x * 128;
    const __half* __restrict__ P = g_p + (size_t)bh * LSEQ * LSEQ;
    const __half* __restrict__ V = g_v + (size_t)bh * LSEQ * HDIM;

    const int tid = threadIdx.x;
    const int wid = tid >> 5, lane = tid & 31;
    const int g = lane >> 2, t = lane & 3;
    const int mw = (wid & 3) * 32, nw = (wid >> 2) * 32;
    const int lr = (lane & 7) + ((lane >> 3) & 1) * 8;
    const int lc = (lane >> 4) * 8;

    const int lrow = tid & 127, lcol = (tid >> 7) << 3;     // P staging
    const __half* pp = P + (size_t)(m0 + lrow) * LSEQ + lcol;

    float acc[2][4][4];
#pragma unroll
    for (int mi = 0; mi < 2; mi++)
#pragma unroll
        for (int ni = 0; ni < 4; ni++)
#pragma unroll
            for (int r = 0; r < 4; r++) acc[mi][ni][r] = 0.f;

    uint4 pa[2];
    __half2 vr[4];
    // prologue: tile 0
    pa[0] = *(const uint4*)(pp);
    pa[1] = *(const uint4*)(pp + 16);
#pragma unroll
    for (int i = 0; i < 4; i++) {
        int idx = tid + 256 * i;
        vr[i] = *(const __half2*)(V + (size_t)(idx >> 5) * HDIM + ((idx & 31) << 1));
    }
    {
        __half* pd = &Ps[0][lrow * 40 + lcol];
        *(uint4*)pd = pa[0]; *(uint4*)(pd + 16) = pa[1];
#pragma unroll
        for (int i = 0; i < 4; i++) {
            int idx = tid + 256 * i;
            int kr = idx >> 5, n = (idx & 31) << 1;
            Vs[0][n * 40 + kr]       = __low2half(vr[i]);
            Vs[0][(n + 1) * 40 + kr] = __high2half(vr[i]);
        }
    }
    __syncthreads();

    const int KT = LSEQ / 32;   // 64
    for (int kt = 0; kt < KT; kt++) {
        const int cur = kt & 1, nxt = cur ^ 1;
        if (kt + 1 < KT) {
            const __half* qp = pp + (kt + 1) * 32;
            pa[0] = *(const uint4*)(qp);
            pa[1] = *(const uint4*)(qp + 16);
#pragma unroll
            for (int i = 0; i < 4; i++) {
                int idx = tid + 256 * i;
                vr[i] = *(const __half2*)(V + (size_t)((kt + 1) * 32 + (idx >> 5)) * HDIM
                                            + ((idx & 31) << 1));
            }
        }

        uint32_t ps_base = (uint32_t)__cvta_generic_to_shared(&Ps[cur][0]);
        uint32_t vs_base = (uint32_t)__cvta_generic_to_shared(&Vs[cur][0]);
#pragma unroll
        for (int ks = 0; ks < 2; ks++) {
            const int kk = ks * 16;
            uint32_t a4[2][4], b4[2][4];
#pragma unroll
            for (int mi = 0; mi < 2; mi++)
                ldm_x4(a4[mi], ps_base + ((mw + 16 * mi + lr) * 40 + kk + lc) * 2);
#pragma unroll
            for (int nj = 0; nj < 2; nj++)
                ldm_x4(b4[nj], vs_base + ((nw + 16 * nj + lr) * 40 + kk + lc) * 2);
#pragma unroll
            for (int mi = 0; mi < 2; mi++)
#pragma unroll
                for (int ni = 0; ni < 4; ni++) {
                    uint32_t bf[2] = {b4[ni >> 1][ni & 1], b4[ni >> 1][(ni & 1) + 2]};
                    mma16(acc[mi][ni], a4[mi], bf, acc[mi][ni]);
                }
        }

        if (kt + 1 < KT) {
            __half* pd = &Ps[nxt][lrow * 40 + lcol];
            *(uint4*)pd = pa[0]; *(uint4*)(pd + 16) = pa[1];
#pragma unroll
            for (int i = 0; i < 4; i++) {
                int idx = tid + 256 * i;
                int kr = idx >> 5, n = (idx & 31) << 1;
                Vs[nxt][n * 40 + kr]       = __low2half(vr[i]);
                Vs[nxt][(n + 1) * 40 + kr] = __high2half(vr[i]);
            }
        }
        __syncthreads();
    }

    const int b = bh >> 4;
    const int h = bh & 15;
#pragma unroll
    for (int mi = 0; mi < 2; mi++) {
        int mA = m0 + mw + 16 * mi + g;
#pragma unroll
        for (int ni = 0; ni < 4; ni++) {
            int d = nw + 8 * ni + 2 * t;
#pragma unroll
            for (int half = 0; half < 2; half++) {
                int qrow = mA + half * 8;
                uint32_t u = pack_h2(acc[mi][ni][half * 2 + 0], acc[mi][ni][half * 2 + 1]);
                *(uint32_t*)&g_ctx[((size_t)qrow * BATCH + b) * DMODEL + h * HDIM + d] = u;
            }
        }
    }
}

// ============================================================================
extern "C" void kernel_launch(void* const* d_in, const int* in_sizes, int n_in,
                              void* d_out, int out_size)
{
    const float* query = (const float*)d_in[0];
    const float* key_  = (const float*)d_in[1];
    const float* value = (const float*)d_in[2];
    const float* Wq = (const float*)d_in[3];
    const float* bq = (const float*)d_in[4];
    const float* Wk = (const float*)d_in[5];
    const float* bk = (const float*)d_in[6];
    const float* Wv = (const float*)d_in[7];
    const float* bv = (const float*)d_in[8];
    const float* Wo = (const float*)d_in[9];
    const float* bo = (const float*)d_in[10];

    float* out = (float*)d_out;                        // (L, B, D)
    float* avg = out + (size_t)MROWS * DMODEL;         // (B, L, L)

    __half *pq, *pk, *pv, *pctx, *pxh, *pwh;
    cudaGetSymbolAddress((void**)&pq,   g_q);
    cudaGetSymbolAddress((void**)&pk,   g_k);
    cudaGetSymbolAddress((void**)&pv,   g_v);
    cudaGetSymbolAddress((void**)&pctx, g_ctx);
    cudaGetSymbolAddress((void**)&pxh,  g_xh);
    cudaGetSymbolAddress((void**)&pwh,  g_wh);

    const size_t XSZ = (size_t)MROWS * DMODEL;     // 8.4M
    const size_t WSZ = (size_t)DMODEL * DMODEL;    // 1.05M

    // fp32 -> fp16 conversions
    const int CB = 256 * 8;
    cvt_f2h<<<(int)((XSZ + CB - 1) / CB), 256>>>(query, pxh + 0 * XSZ, (int)XSZ);
    cvt_f2h<<<(int)((XSZ + CB - 1) / CB), 256>>>(key_,  pxh + 1 * XSZ, (int)XSZ);
    cvt_f2h<<<(int)((XSZ + CB - 1) / CB), 256>>>(value, pxh + 2 * XSZ, (int)XSZ);
    cvt_f2h<<<(int)((WSZ + CB - 1) / CB), 256>>>(Wq, pwh + 0 * WSZ, (int)WSZ);
    cvt_f2h<<<(int)((WSZ + CB - 1) / CB), 256>>>(Wk, pwh + 1 * WSZ, (int)WSZ);
    cvt_f2h<<<(int)((WSZ + CB - 1) / CB), 256>>>(Wv, pwh + 2 * WSZ, (int)WSZ);
    cvt_f2h<<<(int)((WSZ + CB - 1) / CB), 256>>>(Wo, pwh + 3 * WSZ, (int)WSZ);

    const float scaling = 0.125f; // hd^-0.5

    dim3 gp(DMODEL / 128, MROWS / 128);   // (8, 64)
    gemm_h<<<gp, 256>>>(pxh + 0 * XSZ, pwh + 0 * WSZ, bq, pq, scaling, 1);
    gemm_h<<<gp, 256>>>(pxh + 1 * XSZ, pwh + 1 * WSZ, bk, pk, 1.0f,    1);
    gemm_h<<<gp, 256>>>(pxh + 2 * XSZ, pwh + 2 * WSZ, bv, pv, 1.0f,    1);

    scores_h<<<dim3(LSEQ / 128, LSEQ / 128, BHEADS), 256>>>();

    softmax_avg_kernel<<<dim3(LSEQ, BATCH), 256>>>(avg);

    pv_h<<<dim3(LSEQ / 128, BHEADS), 256>>>();

    gemm_h<<<gp, 256>>>(pctx, pwh + 3 * WSZ, bo, out, 1.0f, 0);
}